// round 1
// baseline (speedup 1.0000x reference)
#include <cuda_runtime.h>
#include <cstdint>

// ---------------------------------------------------------------------------
// KAGNMoE: y = conv3x3(silu(gram_basis(tanh(x)))) * top2_gate_scale(x), loss
//   x:            (16, 32, 192, 192) f32
//   w_gate:       (32, 8) f32
//   poly_weights: (1, 32, 128, 3, 3) f32   [OC=32][IC=128][3][3]
//   beta_weights: (4,) f32
// Output: y (16*32*192*192 floats) followed by loss (1 float).
// ---------------------------------------------------------------------------

#define NB 16
#define CI 32
#define HH 192
#define WW 192
#define HW (HH * WW)          // 36864
#define GC 128                // 4 basis * 32 input channels
#define NE 8

// Scratch (no cudaMalloc allowed): ~302 MB for the basis tensor.
__device__ float g_scratch[(size_t)NB * GC * HW];
__device__ float wT_s[GC * 9 * CI];       // [c][k][oc]
__device__ float gate_mean_s[NB * CI];
__device__ float s_scale_s[NB];

__device__ __forceinline__ float silu_f(float v) {
    return v / (1.0f + expf(-v));
}

// ---------------------------------------------------------------------------
// K0: transpose weights [oc][c][k] -> [c][k][oc]
// ---------------------------------------------------------------------------
__global__ void transpose_w_kernel(const float* __restrict__ W) {
    int i = blockIdx.x * 256 + threadIdx.x;
    if (i < CI * GC * 9) {
        int oc = i / (GC * 9);
        int rem = i - oc * (GC * 9);
        int c = rem / 9;
        int k = rem - c * 9;
        wT_s[(c * 9 + k) * CI + oc] = W[i];
    }
}

// ---------------------------------------------------------------------------
// K1: per-(n,ci) spatial mean of x
// ---------------------------------------------------------------------------
__global__ void gate_mean_kernel(const float* __restrict__ x) {
    const int b = blockIdx.x;                 // n*32 + ci  (512 blocks)
    const float* xp = x + (size_t)b * HW;
    float s = 0.0f;
    for (int i = threadIdx.x; i < HW; i += 256) s += xp[i];
    __shared__ float sh[8];
    #pragma unroll
    for (int o = 16; o > 0; o >>= 1) s += __shfl_down_sync(0xffffffffu, s, o);
    if ((threadIdx.x & 31) == 0) sh[threadIdx.x >> 5] = s;
    __syncthreads();
    if (threadIdx.x < 8) {
        s = sh[threadIdx.x];
        #pragma unroll
        for (int o = 4; o > 0; o >>= 1) s += __shfl_down_sync(0xffu, s, o);
        if (threadIdx.x == 0) gate_mean_s[b] = s * (1.0f / 36864.0f);
    }
}

// ---------------------------------------------------------------------------
// K2: gating: logits -> softmax -> top-2 -> per-batch scale + CV^2 loss
// ---------------------------------------------------------------------------
__device__ float cv_sq(const float* v) {
    float m = 0.0f;
    #pragma unroll
    for (int i = 0; i < NE; ++i) m += v[i];
    m *= (1.0f / NE);
    float var = 0.0f;
    #pragma unroll
    for (int i = 0; i < NE; ++i) { float d = v[i] - m; var += d * d; }
    var *= (1.0f / (NE - 1));          // ddof=1
    return var / (m * m + 1e-10f);
}

__global__ void gating_kernel(const float* __restrict__ wg,
                              float* __restrict__ d_out, int loss_idx) {
    __shared__ float sg0[NB], sg1[NB];
    __shared__ int si0[NB], si1[NB];
    int t = threadIdx.x;
    if (t < NB) {
        float l[NE];
        #pragma unroll
        for (int e = 0; e < NE; ++e) {
            float a = 0.0f;
            #pragma unroll
            for (int c = 0; c < CI; ++c) a += gate_mean_s[t * CI + c] * wg[c * NE + e];
            l[e] = a;
        }
        float m = l[0];
        #pragma unroll
        for (int e = 1; e < NE; ++e) m = fmaxf(m, l[e]);
        float p[NE];
        float sum = 0.0f;
        #pragma unroll
        for (int e = 0; e < NE; ++e) { p[e] = expf(l[e] - m); sum += p[e]; }
        float inv = 1.0f / sum;
        #pragma unroll
        for (int e = 0; e < NE; ++e) p[e] *= inv;
        // top-2 (strict > keeps lowest index on ties, matching jax.lax.top_k)
        int i0 = 0; float v0 = p[0];
        #pragma unroll
        for (int e = 1; e < NE; ++e) if (p[e] > v0) { v0 = p[e]; i0 = e; }
        int i1 = -1; float v1 = -1.0f;
        #pragma unroll
        for (int e = 0; e < NE; ++e) if (e != i0 && p[e] > v1) { v1 = p[e]; i1 = e; }
        float invS = 1.0f / (v0 + v1 + 1e-6f);
        sg0[t] = v0 * invS;
        sg1[t] = v1 * invS;
        si0[t] = i0;
        si1[t] = i1;
        s_scale_s[t] = (v0 + v1) * invS;
    }
    __syncthreads();
    if (t == 0) {
        float imp[NE] = {0}, ld[NE] = {0};
        for (int n = 0; n < NB; ++n) {
            imp[si0[n]] += sg0[n];
            imp[si1[n]] += sg1[n];
            ld[si0[n]] += 1.0f;
            ld[si1[n]] += 1.0f;
        }
        d_out[loss_idx] = 0.01f * (cv_sq(imp) + cv_sq(ld));
    }
}

// ---------------------------------------------------------------------------
// K3: basis tensor g = silu(gram(tanh(x))) into scratch, float4 vectorized
//   g layout: [n][p*32+ci][h][w], p = basis index 0..3
// ---------------------------------------------------------------------------
__global__ void basis_kernel(const float* __restrict__ x,
                             const float* __restrict__ bw) {
    const int i = blockIdx.x * 256 + threadIdx.x;   // float4 index, 18874368 total
    const int HW4 = HW / 4;                         // 9216
    const int nc = i / HW4;
    const int p4 = i - nc * HW4;
    const int n = nc >> 5;
    const int ci = nc & 31;

    const float beta2 = 2.25f * bw[1];              // (3*1*1*3/4)
    const float beta3 = (300.0f / 9.0f) * bw[2];    // (5*1*4*15/9)

    float4 xv = reinterpret_cast<const float4*>(x)[i];

    float4 o0, o1, o2, o3;
    {
        float t = tanhf(xv.x);
        float p2 = t * t - beta2, p3 = t * p2 - beta3 * t;
        o0.x = silu_f(1.0f); o1.x = silu_f(t); o2.x = silu_f(p2); o3.x = silu_f(p3);
    }
    {
        float t = tanhf(xv.y);
        float p2 = t * t - beta2, p3 = t * p2 - beta3 * t;
        o0.y = silu_f(1.0f); o1.y = silu_f(t); o2.y = silu_f(p2); o3.y = silu_f(p3);
    }
    {
        float t = tanhf(xv.z);
        float p2 = t * t - beta2, p3 = t * p2 - beta3 * t;
        o0.z = silu_f(1.0f); o1.z = silu_f(t); o2.z = silu_f(p2); o3.z = silu_f(p3);
    }
    {
        float t = tanhf(xv.w);
        float p2 = t * t - beta2, p3 = t * p2 - beta3 * t;
        o0.w = silu_f(1.0f); o1.w = silu_f(t); o2.w = silu_f(p2); o3.w = silu_f(p3);
    }

    float4* g4 = reinterpret_cast<float4*>(g_scratch);
    const size_t base = (size_t)n * GC * HW4 + (size_t)ci * HW4 + p4;
    g4[base + 0 * 32 * HW4] = o0;
    g4[base + 1 * 32 * HW4] = o1;
    g4[base + 2 * 32 * HW4] = o2;
    g4[base + 3 * 32 * HW4] = o3;
}

// ---------------------------------------------------------------------------
// K4: conv 3x3 (IC=128 -> OC=32), pad 1, scaled by s_n.
// CTA: one batch, 16x8 output pixel tile, all 32 OCs.
// 256 threads = 8 warps; lane = oc, warp = output row, 16 px accumulators.
// ---------------------------------------------------------------------------
__global__ __launch_bounds__(256) void conv_kernel(float* __restrict__ out) {
    const int n = blockIdx.z;
    const int x0 = blockIdx.x * 16;   // 12 tiles
    const int y0 = blockIdx.y * 8;    // 24 tiles
    const int tid = threadIdx.x;
    const int lane = tid & 31;        // oc
    const int wid = tid >> 5;         // row within tile

    __shared__ float g_s[8][10][18];  // 8 channels x (8+2) rows x (16+2) cols
    __shared__ float w_s[8 * 9 * 32]; // [cc][k][oc]
    __shared__ float out_s[32 * 129]; // padded stride -> no bank conflicts

    float acc[16];
    #pragma unroll
    for (int p = 0; p < 16; ++p) acc[p] = 0.0f;

    const float* gbase = g_scratch + (size_t)n * GC * HW;

    for (int chunk = 0; chunk < 16; ++chunk) {
        __syncthreads();   // previous iteration's smem reads done
        // weights for this 8-channel chunk (linear copy of transposed slab)
        for (int i = tid; i < 2304; i += 256)
            w_s[i] = wT_s[chunk * 2304 + i];
        // g tile with halo, zero-padded at image borders
        for (int i = tid; i < 1440; i += 256) {
            int cc = i / 180;
            int rem = i - cc * 180;
            int r = rem / 18;
            int cl = rem - r * 18;
            int gy = y0 - 1 + r;
            int gx = x0 - 1 + cl;
            float v = 0.0f;
            if (gy >= 0 && gy < HH && gx >= 0 && gx < WW)
                v = gbase[(size_t)(chunk * 8 + cc) * HW + gy * WW + gx];
            g_s[cc][r][cl] = v;
        }
        __syncthreads();

        #pragma unroll
        for (int cc = 0; cc < 8; ++cc) {
            float w[9];
            #pragma unroll
            for (int k = 0; k < 9; ++k) w[k] = w_s[cc * 288 + k * 32 + lane];
            #pragma unroll
            for (int kh = 0; kh < 3; ++kh) {
                float gr[18];
                #pragma unroll
                for (int j = 0; j < 18; ++j) gr[j] = g_s[cc][wid + kh][j]; // broadcast
                #pragma unroll
                for (int kw = 0; kw < 3; ++kw) {
                    const float wv = w[kh * 3 + kw];
                    #pragma unroll
                    for (int px = 0; px < 16; ++px)
                        acc[px] = fmaf(wv, gr[px + kw], acc[px]);
                }
            }
        }
    }

    const float s = s_scale_s[n];
    #pragma unroll
    for (int px = 0; px < 16; ++px)
        out_s[lane * 129 + wid * 16 + px] = acc[px] * s;
    __syncthreads();

    // coalesced store
    for (int i = tid; i < 4096; i += 256) {
        int oc = i >> 7;
        int rp = i & 127;
        int row = rp >> 4;
        int col = rp & 15;
        out[((size_t)(n * 32 + oc) * HH + (y0 + row)) * WW + (x0 + col)] =
            out_s[oc * 129 + rp];
    }
}

// ---------------------------------------------------------------------------
extern "C" void kernel_launch(void* const* d_in, const int* in_sizes, int n_in,
                              void* d_out, int out_size) {
    const float* x  = (const float*)d_in[0];   // 16*32*192*192
    const float* wg = (const float*)d_in[1];   // 32*8
    const float* W  = (const float*)d_in[2];   // 32*128*3*3
    const float* bw = (const float*)d_in[3];   // 4
    float* out = (float*)d_out;
    const int loss_idx = out_size - 1;         // y then loss

    transpose_w_kernel<<<144, 256>>>(W);
    gate_mean_kernel<<<NB * CI, 256>>>(x);
    gating_kernel<<<1, 32>>>(wg, out, loss_idx);
    basis_kernel<<<(NB * CI * HW / 4) / 256, 256>>>(x, bw);
    dim3 grid(WW / 16, HH / 8, NB);
    conv_kernel<<<grid, 256>>>(out);
}

// round 2
// speedup vs baseline: 1.0154x; 1.0154x over previous
#include <cuda_runtime.h>
#include <cstdint>

typedef unsigned long long ull;

// ---------------------------------------------------------------------------
// KAGNMoE: y = conv3x3(silu(gram_basis(tanh(x)))) * top2_gate_scale(x), loss
//   x:            (16, 32, 192, 192) f32
//   w_gate:       (32, 8) f32
//   poly_weights: (1, 32, 128, 3, 3) f32   [OC=32][IC=128][3][3]
//   beta_weights: (4,) f32
// Output: y (16*32*192*192 floats) followed by loss (1 float).
//
// Round-2 structure:
//  * basis-0 channels are constant silu(1) -> folded into a per-(oc,border)
//    bias; conv reduced from 128 to 96 input channels.
//  * conv inner loop uses packed fma.rn.f32x2 (FFMA2): 2 pixels per instr.
//    g tile stored twice in smem (normal + shifted-by-1) so kw=0/1/2 all read
//    aligned 64-bit pairs via broadcast LDS.64. Weights pre-duplicated (w,w).
// ---------------------------------------------------------------------------

#define NB 16
#define CI 32
#define HH 192
#define WW 192
#define HW (HH * WW)          // 36864
#define GC96 96               // 3 non-constant basis * 32 input channels
#define NE 8

// Scratch (no cudaMalloc allowed): ~226 MB for the non-constant basis tensor.
__device__ float g_scratch[(size_t)NB * GC96 * HW];
__device__ float2 wT2_g[GC96 * 9 * CI];   // [gc][k][oc] duplicated pairs
__device__ float gate_mean_s[NB * CI];
__device__ float s_scale_s[NB];
__device__ float bias_g[9 * CI];          // [ry*3+cx][oc]

__device__ __forceinline__ float silu_f(float v) {
    return v / (1.0f + expf(-v));
}

__device__ __forceinline__ ull fma2(ull a, ull b, ull c) {
    ull d;
    asm("fma.rn.f32x2 %0, %1, %2, %3;" : "=l"(d) : "l"(a), "l"(b), "l"(c));
    return d;
}

// ---------------------------------------------------------------------------
// K0a: weights for channels 32..127 -> [gc][k][oc] as duplicated float2
// ---------------------------------------------------------------------------
__global__ void transpose_w_kernel(const float* __restrict__ W) {
    int i = blockIdx.x * 256 + threadIdx.x;        // 96*9*32 = 27648
    if (i < GC96 * 9 * CI) {
        int gc = i / (9 * CI);
        int rem = i - gc * (9 * CI);
        int k = rem / CI;
        int oc = rem - k * CI;
        float w = W[((size_t)oc * 128 + (32 + gc)) * 9 + k];
        wT2_g[i] = make_float2(w, w);
    }
}

// ---------------------------------------------------------------------------
// K0b: fold constant basis-0 channels into per-(border-type, oc) bias.
// tap (kh,kw) is invalid when the padded input position falls outside.
// ---------------------------------------------------------------------------
__global__ void bias_kernel(const float* __restrict__ W) {
    int oc = threadIdx.x;                          // 32 threads
    float S[9];
    #pragma unroll
    for (int k = 0; k < 9; ++k) S[k] = 0.0f;
    for (int ci = 0; ci < 32; ++ci)
        #pragma unroll
        for (int k = 0; k < 9; ++k)
            S[k] += W[((size_t)oc * 128 + ci) * 9 + k];
    const float c0 = silu_f(1.0f);
    #pragma unroll
    for (int ry = 0; ry < 3; ++ry) {
        #pragma unroll
        for (int cx = 0; cx < 3; ++cx) {
            float b = 0.0f;
            #pragma unroll
            for (int kh = 0; kh < 3; ++kh) {
                if ((ry == 0 && kh == 0) || (ry == 2 && kh == 2)) continue;
                #pragma unroll
                for (int kw = 0; kw < 3; ++kw) {
                    if ((cx == 0 && kw == 0) || (cx == 2 && kw == 2)) continue;
                    b += S[kh * 3 + kw];
                }
            }
            bias_g[(ry * 3 + cx) * CI + oc] = b * c0;
        }
    }
}

// ---------------------------------------------------------------------------
// K1: per-(n,ci) spatial mean of x
// ---------------------------------------------------------------------------
__global__ void gate_mean_kernel(const float* __restrict__ x) {
    const int b = blockIdx.x;                 // n*32 + ci  (512 blocks)
    const float* xp = x + (size_t)b * HW;
    float s = 0.0f;
    for (int i = threadIdx.x; i < HW; i += 256) s += xp[i];
    __shared__ float sh[8];
    #pragma unroll
    for (int o = 16; o > 0; o >>= 1) s += __shfl_down_sync(0xffffffffu, s, o);
    if ((threadIdx.x & 31) == 0) sh[threadIdx.x >> 5] = s;
    __syncthreads();
    if (threadIdx.x < 8) {
        s = sh[threadIdx.x];
        #pragma unroll
        for (int o = 4; o > 0; o >>= 1) s += __shfl_down_sync(0xffu, s, o);
        if (threadIdx.x == 0) gate_mean_s[b] = s * (1.0f / 36864.0f);
    }
}

// ---------------------------------------------------------------------------
// K2: gating: logits -> softmax -> top-2 -> per-batch scale + CV^2 loss
// ---------------------------------------------------------------------------
__device__ float cv_sq(const float* v) {
    float m = 0.0f;
    #pragma unroll
    for (int i = 0; i < NE; ++i) m += v[i];
    m *= (1.0f / NE);
    float var = 0.0f;
    #pragma unroll
    for (int i = 0; i < NE; ++i) { float d = v[i] - m; var += d * d; }
    var *= (1.0f / (NE - 1));          // ddof=1
    return var / (m * m + 1e-10f);
}

__global__ void gating_kernel(const float* __restrict__ wg,
                              float* __restrict__ d_out, int loss_idx) {
    __shared__ float sg0[NB], sg1[NB];
    __shared__ int si0[NB], si1[NB];
    int t = threadIdx.x;
    if (t < NB) {
        float l[NE];
        #pragma unroll
        for (int e = 0; e < NE; ++e) {
            float a = 0.0f;
            #pragma unroll
            for (int c = 0; c < CI; ++c) a += gate_mean_s[t * CI + c] * wg[c * NE + e];
            l[e] = a;
        }
        float m = l[0];
        #pragma unroll
        for (int e = 1; e < NE; ++e) m = fmaxf(m, l[e]);
        float p[NE];
        float sum = 0.0f;
        #pragma unroll
        for (int e = 0; e < NE; ++e) { p[e] = expf(l[e] - m); sum += p[e]; }
        float inv = 1.0f / sum;
        #pragma unroll
        for (int e = 0; e < NE; ++e) p[e] *= inv;
        // top-2 (strict > keeps lowest index on ties, matching jax.lax.top_k)
        int i0 = 0; float v0 = p[0];
        #pragma unroll
        for (int e = 1; e < NE; ++e) if (p[e] > v0) { v0 = p[e]; i0 = e; }
        int i1 = -1; float v1 = -1.0f;
        #pragma unroll
        for (int e = 0; e < NE; ++e) if (e != i0 && p[e] > v1) { v1 = p[e]; i1 = e; }
        float invS = 1.0f / (v0 + v1 + 1e-6f);
        sg0[t] = v0 * invS;
        sg1[t] = v1 * invS;
        si0[t] = i0;
        si1[t] = i1;
        s_scale_s[t] = (v0 + v1) * invS;
    }
    __syncthreads();
    if (t == 0) {
        float imp[NE] = {0}, ld[NE] = {0};
        for (int n = 0; n < NB; ++n) {
            imp[si0[n]] += sg0[n];
            imp[si1[n]] += sg1[n];
            ld[si0[n]] += 1.0f;
            ld[si1[n]] += 1.0f;
        }
        d_out[loss_idx] = 0.01f * (cv_sq(imp) + cv_sq(ld));
    }
}

// ---------------------------------------------------------------------------
// K3: basis tensor g = silu(gram(tanh(x))) for p=1..3 only, float4 vectorized
//   g layout: [n][(p-1)*32+ci][h][w]
// ---------------------------------------------------------------------------
__global__ void basis_kernel(const float* __restrict__ x,
                             const float* __restrict__ bw) {
    const int i = blockIdx.x * 256 + threadIdx.x;   // float4 index, 4718592 total
    const int HW4 = HW / 4;                         // 9216
    const int nc = i / HW4;
    const int p4 = i - nc * HW4;
    const int n = nc >> 5;
    const int ci = nc & 31;

    const float beta2 = 2.25f * bw[1];              // (3*1*1*3/4)
    const float beta3 = (300.0f / 9.0f) * bw[2];    // (5*1*4*15/9)

    float4 xv = reinterpret_cast<const float4*>(x)[i];

    float4 o1, o2, o3;
    {
        float t = tanhf(xv.x);
        float p2 = t * t - beta2, p3 = t * p2 - beta3 * t;
        o1.x = silu_f(t); o2.x = silu_f(p2); o3.x = silu_f(p3);
    }
    {
        float t = tanhf(xv.y);
        float p2 = t * t - beta2, p3 = t * p2 - beta3 * t;
        o1.y = silu_f(t); o2.y = silu_f(p2); o3.y = silu_f(p3);
    }
    {
        float t = tanhf(xv.z);
        float p2 = t * t - beta2, p3 = t * p2 - beta3 * t;
        o1.z = silu_f(t); o2.z = silu_f(p2); o3.z = silu_f(p3);
    }
    {
        float t = tanhf(xv.w);
        float p2 = t * t - beta2, p3 = t * p2 - beta3 * t;
        o1.w = silu_f(t); o2.w = silu_f(p2); o3.w = silu_f(p3);
    }

    float4* g4 = reinterpret_cast<float4*>(g_scratch);
    const size_t base = (size_t)n * GC96 * HW4 + (size_t)ci * HW4 + p4;
    g4[base + 0 * 32 * HW4] = o1;
    g4[base + 1 * 32 * HW4] = o2;
    g4[base + 2 * 32 * HW4] = o3;
}

// ---------------------------------------------------------------------------
// K4: conv 3x3 (IC=96 -> OC=32), pad 1, + basis0 bias, scaled by s_n.
// CTA: one batch, 16x16 output pixel tile, all 32 OCs.
// 256 threads = 8 warps; lane = oc, warp wid -> output rows 2wid, 2wid+1.
// Packed f32x2: 8 pixel-pair accumulators per output row.
// smem: E tile (normal), O tile (shifted by 1 col), duplicated weight pairs.
// ---------------------------------------------------------------------------
#define SM_E 0
#define SM_O 10368
#define SM_W 20736
#define SM_BYTES 39168           // max(E+O+W, out staging 32*257*4=32896)

__global__ __launch_bounds__(256) void conv_kernel(float* __restrict__ out) {
    const int n = blockIdx.z;
    const int x0 = blockIdx.x * 16;   // 12 tiles
    const int y0 = blockIdx.y * 16;   // 12 tiles
    const int tid = threadIdx.x;
    const int lane = tid & 31;        // oc
    const int wid = tid >> 5;

    __shared__ __align__(16) unsigned char sraw[SM_BYTES];
    float* E_s = (float*)(sraw + SM_E);       // [8][18][18]
    float* O_s = (float*)(sraw + SM_O);       // [8][18][18] (cols 0..15 used)
    ull*   w_s = (ull*)(sraw + SM_W);         // [8][9][32]
    float* out_s = (float*)sraw;              // [32][257] epilogue alias

    ull acc[2][8];
    #pragma unroll
    for (int rr = 0; rr < 2; ++rr)
        #pragma unroll
        for (int p = 0; p < 8; ++p) acc[rr][p] = 0ull;

    const float* gbase = g_scratch + (size_t)n * GC96 * HW;
    const ull* wsrc = (const ull*)wT2_g;

    for (int ch = 0; ch < 12; ++ch) {
        __syncthreads();
        // duplicated weight pairs for this 8-channel chunk
        for (int i = tid; i < 2304; i += 256)
            w_s[i] = wsrc[ch * 2304 + i];
        // g tile with halo into E (normal) and O (shift-by-1) layouts
        for (int i = tid; i < 2592; i += 256) {
            int cc = i / 324;
            int rem = i - cc * 324;
            int r = rem / 18;
            int c = rem - r * 18;
            int gy = y0 - 1 + r;
            int gx = x0 - 1 + c;
            float v = 0.0f;
            if (gy >= 0 && gy < HH && gx >= 0 && gx < WW)
                v = gbase[(size_t)(ch * 8 + cc) * HW + gy * WW + gx];
            E_s[(cc * 18 + r) * 18 + c] = v;
            if (c >= 1 && c < 17)
                O_s[(cc * 18 + r) * 18 + (c - 1)] = v;
        }
        __syncthreads();

        #pragma unroll
        for (int cc = 0; cc < 8; ++cc) {
            ull wp[9];
            #pragma unroll
            for (int k = 0; k < 9; ++k)
                wp[k] = w_s[(cc * 9 + k) * 32 + lane];
            #pragma unroll
            for (int R = 0; R < 4; ++R) {
                const float* er = &E_s[(cc * 18 + 2 * wid + R) * 18];
                const float* orw = &O_s[(cc * 18 + 2 * wid + R) * 18];
                ull e[9], o[8];
                #pragma unroll
                for (int p = 0; p < 9; ++p)
                    e[p] = *(const ull*)(er + 2 * p);      // broadcast LDS.64
                #pragma unroll
                for (int p = 0; p < 8; ++p)
                    o[p] = *(const ull*)(orw + 2 * p);
                #pragma unroll
                for (int rr = 0; rr < 2; ++rr) {
                    const int kh = R - rr;                 // compile-time
                    if (kh >= 0 && kh <= 2) {
                        #pragma unroll
                        for (int p = 0; p < 8; ++p) {
                            acc[rr][p] = fma2(wp[kh * 3 + 0], e[p],     acc[rr][p]);
                            acc[rr][p] = fma2(wp[kh * 3 + 1], o[p],     acc[rr][p]);
                            acc[rr][p] = fma2(wp[kh * 3 + 2], e[p + 1], acc[rr][p]);
                        }
                    }
                }
            }
        }
    }

    // epilogue: bias + scale, stage to smem, coalesced store
    float bloc[9];
    #pragma unroll
    for (int j = 0; j < 9; ++j) bloc[j] = bias_g[j * 32 + lane];
    const float s = s_scale_s[n];
    __syncthreads();   // all smem reads done before aliasing to out_s

    #pragma unroll
    for (int rr = 0; rr < 2; ++rr) {
        const int trow = 2 * wid + rr;
        const int y = y0 + trow;
        const int ry = (y == 0) ? 0 : ((y == HH - 1) ? 2 : 1);
        #pragma unroll
        for (int p = 0; p < 8; ++p) {
            float lo = __uint_as_float((unsigned)(acc[rr][p] & 0xffffffffu));
            float hi = __uint_as_float((unsigned)(acc[rr][p] >> 32));
            const int xlo = x0 + 2 * p;
            const int xhi = xlo + 1;
            const int cxl = (xlo == 0) ? 0 : ((xlo == WW - 1) ? 2 : 1);
            const int cxh = (xhi == 0) ? 0 : ((xhi == WW - 1) ? 2 : 1);
            out_s[lane * 257 + trow * 16 + 2 * p]     = (lo + bloc[ry * 3 + cxl]) * s;
            out_s[lane * 257 + trow * 16 + 2 * p + 1] = (hi + bloc[ry * 3 + cxh]) * s;
        }
    }
    __syncthreads();

    for (int i = tid; i < 8192; i += 256) {
        int oc = i >> 8;
        int idx = i & 255;
        int row = idx >> 4;
        int col = idx & 15;
        out[((size_t)(n * 32 + oc) * HH + (y0 + row)) * WW + (x0 + col)] =
            out_s[oc * 257 + idx];
    }
}

// ---------------------------------------------------------------------------
extern "C" void kernel_launch(void* const* d_in, const int* in_sizes, int n_in,
                              void* d_out, int out_size) {
    const float* x  = (const float*)d_in[0];   // 16*32*192*192
    const float* wg = (const float*)d_in[1];   // 32*8
    const float* W  = (const float*)d_in[2];   // 32*128*3*3
    const float* bw = (const float*)d_in[3];   // 4
    float* out = (float*)d_out;
    const int loss_idx = out_size - 1;         // y then loss

    transpose_w_kernel<<<108, 256>>>(W);
    bias_kernel<<<1, 32>>>(W);
    gate_mean_kernel<<<NB * CI, 256>>>(x);
    gating_kernel<<<1, 32>>>(wg, out, loss_idx);
    basis_kernel<<<(NB * CI * HW / 4) / 256, 256>>>(x, bw);
    dim3 grid(WW / 16, HH / 16, NB);
    conv_kernel<<<grid, 256>>>(out);
}

// round 3
// speedup vs baseline: 1.6088x; 1.5844x over previous
#include <cuda_runtime.h>
#include <cstdint>

// ---------------------------------------------------------------------------
// KAGNMoE: y = conv3x3(silu(gram_basis(tanh(x)))) * top2_gate_scale(x), loss
// Round 3: conv as implicit GEMM on tensor cores (mma.sync m16n8k8 tf32).
//   basis-0 folded to fp32 bias; 96 effective input channels.
//   g scratch + weights pre-rounded to tf32 (RNA); fp32 accumulation.
// ---------------------------------------------------------------------------

#define NB 16
#define CI 32
#define HH 192
#define WW 192
#define HW (HH * WW)          // 36864
#define GC96 96
#define NE 8

// ~226 MB scratch for the non-constant basis tensor (tf32-rounded values).
__device__ float g_scratch[(size_t)NB * GC96 * HW];
__device__ float w_prep[12 * 9 * 8 * 40];   // [chunk][tap][cc][40] tf32 vals
__device__ float gate_mean_s[NB * CI];
__device__ float s_scale_s[NB];
__device__ float bias_g[9 * CI];            // [ry*3+cx][oc], full fp32

__device__ __forceinline__ float silu_f(float v) {
    return v / (1.0f + expf(-v));
}
__device__ __forceinline__ float to_tf32(float v) {
    float r;
    asm("cvt.rna.tf32.f32 %0, %1;" : "=f"(r) : "f"(v));
    return r;
}
__device__ __forceinline__ void mma_tf32(float* d,
                                         unsigned a0, unsigned a1,
                                         unsigned a2, unsigned a3,
                                         unsigned b0, unsigned b1) {
    asm("mma.sync.aligned.m16n8k8.row.col.f32.tf32.tf32.f32 "
        "{%0,%1,%2,%3}, {%4,%5,%6,%7}, {%8,%9}, {%0,%1,%2,%3};"
        : "+f"(d[0]), "+f"(d[1]), "+f"(d[2]), "+f"(d[3])
        : "r"(a0), "r"(a1), "r"(a2), "r"(a3), "r"(b0), "r"(b1));
}

// ---------------------------------------------------------------------------
// K0: basis tensor (tf32-rounded) + weight prep + bias (last block).
// ---------------------------------------------------------------------------
__global__ void basis_prep_kernel(const float* __restrict__ x,
                                  const float* __restrict__ bw,
                                  const float* __restrict__ W) {
    const int HW4 = HW / 4;                       // 9216
    const int tid = threadIdx.x;

    if (blockIdx.x == gridDim.x - 1) {
        // ---- weight prep: w_prep[ch][tap][cc][oc] = tf32(W[oc][32+ch*8+cc][tap])
        for (int j = tid; j < 12 * 9 * 8 * 32; j += 256) {
            int ch = j / (9 * 8 * 32);
            int r0 = j - ch * (9 * 8 * 32);
            int tap = r0 / (8 * 32);
            int r1 = r0 - tap * (8 * 32);
            int cc = r1 / 32;
            int oc = r1 - cc * 32;
            float w = W[((size_t)oc * 128 + 32 + ch * 8 + cc) * 9 + tap];
            w_prep[((ch * 9 + tap) * 8 + cc) * 40 + oc] = to_tf32(w);
        }
        // ---- basis-0 bias (fp32 exact)
        if (tid < 32) {
            int oc = tid;
            float S[9];
            #pragma unroll
            for (int k = 0; k < 9; ++k) S[k] = 0.0f;
            for (int ci = 0; ci < 32; ++ci)
                #pragma unroll
                for (int k = 0; k < 9; ++k)
                    S[k] += W[((size_t)oc * 128 + ci) * 9 + k];
            const float c0 = silu_f(1.0f);
            #pragma unroll
            for (int ry = 0; ry < 3; ++ry)
                #pragma unroll
                for (int cx = 0; cx < 3; ++cx) {
                    float b = 0.0f;
                    #pragma unroll
                    for (int kh = 0; kh < 3; ++kh) {
                        if ((ry == 0 && kh == 0) || (ry == 2 && kh == 2)) continue;
                        #pragma unroll
                        for (int kw = 0; kw < 3; ++kw) {
                            if ((cx == 0 && kw == 0) || (cx == 2 && kw == 2)) continue;
                            b += S[kh * 3 + kw];
                        }
                    }
                    bias_g[(ry * 3 + cx) * CI + oc] = b * c0;
                }
        }
        return;
    }

    const int i = blockIdx.x * 256 + tid;          // float4 index
    const int nc = i / HW4;
    const int p4 = i - nc * HW4;
    const int n = nc >> 5;
    const int ci = nc & 31;

    const float beta2 = 2.25f * bw[1];
    const float beta3 = (300.0f / 9.0f) * bw[2];

    float4 xv = reinterpret_cast<const float4*>(x)[i];

    float4 o1, o2, o3;
    {
        float t = tanhf(xv.x);
        float p2 = t * t - beta2, p3 = t * p2 - beta3 * t;
        o1.x = to_tf32(silu_f(t)); o2.x = to_tf32(silu_f(p2)); o3.x = to_tf32(silu_f(p3));
    }
    {
        float t = tanhf(xv.y);
        float p2 = t * t - beta2, p3 = t * p2 - beta3 * t;
        o1.y = to_tf32(silu_f(t)); o2.y = to_tf32(silu_f(p2)); o3.y = to_tf32(silu_f(p3));
    }
    {
        float t = tanhf(xv.z);
        float p2 = t * t - beta2, p3 = t * p2 - beta3 * t;
        o1.z = to_tf32(silu_f(t)); o2.z = to_tf32(silu_f(p2)); o3.z = to_tf32(silu_f(p3));
    }
    {
        float t = tanhf(xv.w);
        float p2 = t * t - beta2, p3 = t * p2 - beta3 * t;
        o1.w = to_tf32(silu_f(t)); o2.w = to_tf32(silu_f(p2)); o3.w = to_tf32(silu_f(p3));
    }

    float4* g4 = reinterpret_cast<float4*>(g_scratch);
    const size_t base = (size_t)n * GC96 * HW4 + (size_t)ci * HW4 + p4;
    g4[base + 0 * 32 * HW4] = o1;
    g4[base + 1 * 32 * HW4] = o2;
    g4[base + 2 * 32 * HW4] = o3;
}

// ---------------------------------------------------------------------------
// K1: per-(n,ci) spatial mean of x
// ---------------------------------------------------------------------------
__global__ void gate_mean_kernel(const float* __restrict__ x) {
    const int b = blockIdx.x;
    const float* xp = x + (size_t)b * HW;
    float s = 0.0f;
    for (int i = threadIdx.x; i < HW; i += 256) s += xp[i];
    __shared__ float sh[8];
    #pragma unroll
    for (int o = 16; o > 0; o >>= 1) s += __shfl_down_sync(0xffffffffu, s, o);
    if ((threadIdx.x & 31) == 0) sh[threadIdx.x >> 5] = s;
    __syncthreads();
    if (threadIdx.x < 8) {
        s = sh[threadIdx.x];
        #pragma unroll
        for (int o = 4; o > 0; o >>= 1) s += __shfl_down_sync(0xffu, s, o);
        if (threadIdx.x == 0) gate_mean_s[b] = s * (1.0f / 36864.0f);
    }
}

// ---------------------------------------------------------------------------
// K2: gating
// ---------------------------------------------------------------------------
__device__ float cv_sq(const float* v) {
    float m = 0.0f;
    #pragma unroll
    for (int i = 0; i < NE; ++i) m += v[i];
    m *= (1.0f / NE);
    float var = 0.0f;
    #pragma unroll
    for (int i = 0; i < NE; ++i) { float d = v[i] - m; var += d * d; }
    var *= (1.0f / (NE - 1));
    return var / (m * m + 1e-10f);
}

__global__ void gating_kernel(const float* __restrict__ wg,
                              float* __restrict__ d_out, int loss_idx) {
    __shared__ float sg0[NB], sg1[NB];
    __shared__ int si0[NB], si1[NB];
    int t = threadIdx.x;
    if (t < NB) {
        float l[NE];
        #pragma unroll
        for (int e = 0; e < NE; ++e) {
            float a = 0.0f;
            #pragma unroll
            for (int c = 0; c < CI; ++c) a += gate_mean_s[t * CI + c] * wg[c * NE + e];
            l[e] = a;
        }
        float m = l[0];
        #pragma unroll
        for (int e = 1; e < NE; ++e) m = fmaxf(m, l[e]);
        float p[NE];
        float sum = 0.0f;
        #pragma unroll
        for (int e = 0; e < NE; ++e) { p[e] = expf(l[e] - m); sum += p[e]; }
        float inv = 1.0f / sum;
        #pragma unroll
        for (int e = 0; e < NE; ++e) p[e] *= inv;
        int i0 = 0; float v0 = p[0];
        #pragma unroll
        for (int e = 1; e < NE; ++e) if (p[e] > v0) { v0 = p[e]; i0 = e; }
        int i1 = -1; float v1 = -1.0f;
        #pragma unroll
        for (int e = 0; e < NE; ++e) if (e != i0 && p[e] > v1) { v1 = p[e]; i1 = e; }
        float invS = 1.0f / (v0 + v1 + 1e-6f);
        sg0[t] = v0 * invS;
        sg1[t] = v1 * invS;
        si0[t] = i0;
        si1[t] = i1;
        s_scale_s[t] = (v0 + v1) * invS;
    }
    __syncthreads();
    if (t == 0) {
        float imp[NE] = {0}, ld[NE] = {0};
        for (int n = 0; n < NB; ++n) {
            imp[si0[n]] += sg0[n];
            imp[si1[n]] += sg1[n];
            ld[si0[n]] += 1.0f;
            ld[si1[n]] += 1.0f;
        }
        d_out[loss_idx] = 0.01f * (cv_sq(imp) + cv_sq(ld));
    }
}

// ---------------------------------------------------------------------------
// K3: conv via mma.sync m16n8k8 tf32.
// CTA: 16x16 pixel tile x 2 images x all 32 oc. 8 warps.
// Warp wid: pixel rows {2wid, 2wid+1}. K-step = one tap (kh,kw) x 8 channels.
// smem: gt[2][8][18][20] (cc-stride 360 == 8 mod 32 -> conflict-free frags),
//       ws[9][8][40]     (cc-stride 40  == 8 mod 32 -> conflict-free).
// ---------------------------------------------------------------------------
__global__ __launch_bounds__(256) void conv_kernel(float* __restrict__ out) {
    const int n0 = blockIdx.z * 2;
    const int x0 = blockIdx.x * 16;
    const int y0 = blockIdx.y * 16;
    const int tid = threadIdx.x;
    const int lane = tid & 31;
    const int wid = tid >> 5;
    const int g = lane >> 2;      // groupID
    const int t = lane & 3;       // threadID_in_group

    __shared__ float gt[2 * 2880];    // [img][cc][18][20]
    __shared__ float ws[2880];        // [tap][cc][40]

    float acc[2][2][4][4];
    #pragma unroll
    for (int a = 0; a < 2; ++a)
        #pragma unroll
        for (int b = 0; b < 2; ++b)
            #pragma unroll
            for (int c = 0; c < 4; ++c)
                #pragma unroll
                for (int d = 0; d < 4; ++d) acc[a][b][c][d] = 0.0f;

    for (int ch = 0; ch < 12; ++ch) {
        __syncthreads();
        for (int i = tid; i < 2880; i += 256) ws[i] = w_prep[ch * 2880 + i];
        for (int i = tid; i < 5184; i += 256) {
            int img = i / 2592;
            int rem = i - img * 2592;
            int cc = rem / 324;
            rem -= cc * 324;
            int r = rem / 18;
            int c = rem - r * 18;
            int gy = y0 - 1 + r;
            int gx = x0 - 1 + c;
            float v = 0.0f;
            if (gy >= 0 && gy < HH && gx >= 0 && gx < WW)
                v = g_scratch[((size_t)(n0 + img) * GC96 + ch * 8 + cc) * HW + gy * WW + gx];
            gt[img * 2880 + cc * 360 + r * 20 + c] = v;
        }
        __syncthreads();

        #pragma unroll
        for (int kh = 0; kh < 3; ++kh) {
            #pragma unroll
            for (int kw = 0; kw < 3; ++kw) {
                const int tap = kh * 3 + kw;
                unsigned b0[4], b1[4];
                #pragma unroll
                for (int nc = 0; nc < 4; ++nc) {
                    b0[nc] = __float_as_uint(ws[tap * 320 + t * 40 + 8 * nc + g]);
                    b1[nc] = __float_as_uint(ws[tap * 320 + (t + 4) * 40 + 8 * nc + g]);
                }
                #pragma unroll
                for (int img = 0; img < 2; ++img) {
                    #pragma unroll
                    for (int mrow = 0; mrow < 2; ++mrow) {
                        const float* base =
                            &gt[img * 2880 + t * 360 + (2 * wid + mrow + kh) * 20 + kw];
                        unsigned a0 = __float_as_uint(base[g]);
                        unsigned a1 = __float_as_uint(base[g + 8]);
                        unsigned a2 = __float_as_uint(base[1440 + g]);
                        unsigned a3 = __float_as_uint(base[1440 + g + 8]);
                        #pragma unroll
                        for (int nc = 0; nc < 4; ++nc)
                            mma_tf32(acc[img][mrow][nc], a0, a1, a2, a3, b0[nc], b1[nc]);
                    }
                }
            }
        }
    }

    // epilogue: + basis0 bias, * gate scale, direct stores
    #pragma unroll
    for (int img = 0; img < 2; ++img) {
        const float s = s_scale_s[n0 + img];
        #pragma unroll
        for (int mrow = 0; mrow < 2; ++mrow) {
            const int y = y0 + 2 * wid + mrow;
            const int ry = (y == 0) ? 0 : ((y == HH - 1) ? 2 : 1);
            #pragma unroll
            for (int nc = 0; nc < 4; ++nc) {
                #pragma unroll
                for (int e = 0; e < 4; ++e) {
                    const int px = g + ((e >= 2) ? 8 : 0);
                    const int oc = 8 * nc + 2 * t + (e & 1);
                    const int x = x0 + px;
                    const int cx = (x == 0) ? 0 : ((x == WW - 1) ? 2 : 1);
                    const float val =
                        (acc[img][mrow][nc][e] + bias_g[(ry * 3 + cx) * CI + oc]) * s;
                    out[((size_t)((n0 + img) * CI + oc) * HH + y) * WW + x] = val;
                }
            }
        }
    }
}

// ---------------------------------------------------------------------------
extern "C" void kernel_launch(void* const* d_in, const int* in_sizes, int n_in,
                              void* d_out, int out_size) {
    const float* x  = (const float*)d_in[0];
    const float* wg = (const float*)d_in[1];
    const float* W  = (const float*)d_in[2];
    const float* bw = (const float*)d_in[3];
    float* out = (float*)d_out;
    const int loss_idx = out_size - 1;

    basis_prep_kernel<<<(NB * CI * HW / 4) / 256 + 1, 256>>>(x, bw, W);
    gate_mean_kernel<<<NB * CI, 256>>>(x);
    gating_kernel<<<1, 32>>>(wg, out, loss_idx);
    dim3 grid(WW / 16, HH / 16, NB / 2);
    conv_kernel<<<grid, 256>>>(out);
}

// round 6
// speedup vs baseline: 1.7849x; 1.1095x over previous
#include <cuda_runtime.h>
#include <cstdint>

// ---------------------------------------------------------------------------
// KAGNMoE round 5 (= round-4 design, rebench after infra failure):
// tensor-core conv with ldmatrix A-fragments + cp.async double buffering;
// channel-last basis scratch; fused gating.
// ---------------------------------------------------------------------------

#define NB 16
#define CI 32
#define HH 192
#define WW 192
#define HW (HH * WW)
#define GC96 96
#define NE 8

// channel-last basis scratch: [n][h][w][96] (tf32-rounded), ~226 MB
__device__ float g_scratch[(size_t)NB * HH * WW * GC96];
__device__ float w_prep[12 * 9 * 8 * 40];   // [chunk][tap][cc][40] tf32
__device__ float gate_acc[NB * CI];
__device__ float gate_mean_s[NB * CI];
__device__ float s_scale_s[NB];
__device__ float bias_g[9 * CI];
__device__ unsigned int blk_ctr;

__device__ __forceinline__ float silu_f(float v) { return v / (1.0f + expf(-v)); }
__device__ __forceinline__ float to_tf32(float v) {
    float r; asm("cvt.rna.tf32.f32 %0, %1;" : "=f"(r) : "f"(v)); return r;
}
__device__ __forceinline__ void mma_tf32(float* d, unsigned a0, unsigned a1,
                                         unsigned a2, unsigned a3,
                                         unsigned b0, unsigned b1) {
    asm("mma.sync.aligned.m16n8k8.row.col.f32.tf32.tf32.f32 "
        "{%0,%1,%2,%3}, {%4,%5,%6,%7}, {%8,%9}, {%0,%1,%2,%3};"
        : "+f"(d[0]), "+f"(d[1]), "+f"(d[2]), "+f"(d[3])
        : "r"(a0), "r"(a1), "r"(a2), "r"(a3), "r"(b0), "r"(b1));
}
__device__ __forceinline__ void cp16(uint32_t dst, const void* src, int sz) {
    asm volatile("cp.async.ca.shared.global [%0], [%1], 16, %2;"
                 :: "r"(dst), "l"(src), "r"(sz));
}
#define CP_COMMIT() asm volatile("cp.async.commit_group;")
#define CP_WAIT(n)  asm volatile("cp.async.wait_group %0;" :: "n"(n))

// ---------------------------------------------------------------------------
// K0: zero gate accumulators + counter (graph-replay determinism)
// ---------------------------------------------------------------------------
__global__ void zero_kernel() {
    gate_acc[threadIdx.x] = 0.0f;
    if (threadIdx.x == 0) blk_ctr = 0u;
}

// ---------------------------------------------------------------------------
// K1: weight prep (tf32, [chunk][tap][cc][40]) + basis-0 bias (last block)
// ---------------------------------------------------------------------------
__global__ void prep_kernel(const float* __restrict__ W) {
    if (blockIdx.x < 108) {
        int j = blockIdx.x * 256 + threadIdx.x;    // < 27648
        int ch = j / (9 * 8 * 32);
        int r0 = j - ch * (9 * 8 * 32);
        int tap = r0 / 256;
        int r1 = r0 - tap * 256;
        int cc = r1 >> 5;
        int oc = r1 & 31;
        float w = W[((size_t)oc * 128 + 32 + ch * 8 + cc) * 9 + tap];
        w_prep[((ch * 9 + tap) * 8 + cc) * 40 + oc] = to_tf32(w);
        return;
    }
    int oc = threadIdx.x;
    if (oc >= 32) return;
    float S[9];
    #pragma unroll
    for (int k = 0; k < 9; ++k) S[k] = 0.0f;
    for (int ci = 0; ci < 32; ++ci)
        #pragma unroll
        for (int k = 0; k < 9; ++k)
            S[k] += W[((size_t)oc * 128 + ci) * 9 + k];
    const float c0 = silu_f(1.0f);
    #pragma unroll
    for (int ry = 0; ry < 3; ++ry)
        #pragma unroll
        for (int cx = 0; cx < 3; ++cx) {
            float b = 0.0f;
            #pragma unroll
            for (int kh = 0; kh < 3; ++kh) {
                if ((ry == 0 && kh == 0) || (ry == 2 && kh == 2)) continue;
                #pragma unroll
                for (int kw = 0; kw < 3; ++kw) {
                    if ((cx == 0 && kw == 0) || (cx == 2 && kw == 2)) continue;
                    b += S[kh * 3 + kw];
                }
            }
            bias_g[(ry * 3 + cx) * CI + oc] = b * c0;
        }
}

// ---------------------------------------------------------------------------
// K2: basis (channel-last, tf32) + gate partial sums; last block: gating+loss
// grid (3, 192, 16): (w-chunk of 64, h, n). 256 threads = 4 ci-sub x 64 px.
// ---------------------------------------------------------------------------
__device__ float cv_sq(const float* v) {
    float m = 0.0f;
    #pragma unroll
    for (int i = 0; i < NE; ++i) m += v[i];
    m *= (1.0f / NE);
    float var = 0.0f;
    #pragma unroll
    for (int i = 0; i < NE; ++i) { float d = v[i] - m; var += d * d; }
    var *= (1.0f / (NE - 1));
    return var / (m * m + 1e-10f);
}

__global__ __launch_bounds__(256) void basis_kernel(const float* __restrict__ x,
                                                    const float* __restrict__ bw,
                                                    const float* __restrict__ wg,
                                                    float* __restrict__ d_out,
                                                    int loss_idx) {
    const int n = blockIdx.z, h = blockIdx.y, w0 = blockIdx.x * 64;
    const int tid = threadIdx.x;
    const int cisub = tid >> 6;
    const int pix = tid & 63;

    __shared__ float st[64 * 97];
    const float beta2 = 2.25f * bw[1];
    const float beta3 = (300.0f / 9.0f) * bw[2];

    #pragma unroll
    for (int it = 0; it < 8; ++it) {
        const int ci = it * 4 + cisub;
        float v = x[((size_t)(n * CI + ci) * HH + h) * WW + w0 + pix];
        // gate partial: warp = fixed ci, 32 consecutive pixels
        float ws = v;
        #pragma unroll
        for (int o = 16; o > 0; o >>= 1) ws += __shfl_down_sync(0xffffffffu, ws, o);
        if ((tid & 31) == 0) atomicAdd(&gate_acc[n * CI + ci], ws);
        float t = tanhf(v);
        float p2 = t * t - beta2;
        float p3 = t * p2 - beta3 * t;
        st[pix * 97 + ci]      = to_tf32(silu_f(t));
        st[pix * 97 + 32 + ci] = to_tf32(silu_f(p2));
        st[pix * 97 + 64 + ci] = to_tf32(silu_f(p3));
    }
    __syncthreads();

    float* gout = g_scratch + ((size_t)(n * HH + h) * WW + w0) * GC96;
    #pragma unroll
    for (int it = 0; it < 24; ++it) {
        int f = it * 256 + tid;
        int p = f / 96, c = f - p * 96;
        gout[f] = st[p * 97 + c];
    }

    // ---- last block: finalize means + gating + loss
    __shared__ unsigned int s_last;
    __threadfence();
    __syncthreads();
    if (tid == 0) s_last = atomicAdd(&blk_ctr, 1u);
    __syncthreads();
    if (s_last != 3u * 192u * 16u - 1u) return;
    __threadfence();
    gate_mean_s[tid] = gate_acc[tid] * (1.0f / 36864.0f);
    gate_mean_s[tid + 256] = gate_acc[tid + 256] * (1.0f / 36864.0f);
    __syncthreads();

    __shared__ float sg0[NB], sg1[NB];
    __shared__ int si0[NB], si1[NB];
    if (tid < NB) {
        float l[NE];
        #pragma unroll
        for (int e = 0; e < NE; ++e) {
            float a = 0.0f;
            #pragma unroll
            for (int c = 0; c < CI; ++c) a += gate_mean_s[tid * CI + c] * wg[c * NE + e];
            l[e] = a;
        }
        float m = l[0];
        #pragma unroll
        for (int e = 1; e < NE; ++e) m = fmaxf(m, l[e]);
        float p[NE]; float sum = 0.0f;
        #pragma unroll
        for (int e = 0; e < NE; ++e) { p[e] = expf(l[e] - m); sum += p[e]; }
        float inv = 1.0f / sum;
        #pragma unroll
        for (int e = 0; e < NE; ++e) p[e] *= inv;
        int i0 = 0; float v0 = p[0];
        #pragma unroll
        for (int e = 1; e < NE; ++e) if (p[e] > v0) { v0 = p[e]; i0 = e; }
        int i1 = -1; float v1 = -1.0f;
        #pragma unroll
        for (int e = 0; e < NE; ++e) if (e != i0 && p[e] > v1) { v1 = p[e]; i1 = e; }
        float invS = 1.0f / (v0 + v1 + 1e-6f);
        sg0[tid] = v0 * invS; sg1[tid] = v1 * invS;
        si0[tid] = i0; si1[tid] = i1;
        s_scale_s[tid] = (v0 + v1) * invS;
    }
    __syncthreads();
    if (tid == 0) {
        float imp[NE] = {0}, ld[NE] = {0};
        for (int b = 0; b < NB; ++b) {
            imp[si0[b]] += sg0[b]; imp[si1[b]] += sg1[b];
            ld[si0[b]] += 1.0f;    ld[si1[b]] += 1.0f;
        }
        d_out[loss_idx] = 0.01f * (cv_sq(imp) + cv_sq(ld));
    }
}

// ---------------------------------------------------------------------------
// K3: conv via mma m16n8k8 tf32, ldmatrix A-frags, cp.async double buffer.
// CTA: 16x16 px x 2 imgs x 32 oc. smem buffer (floats):
//   gt: [img][plane][18r][20c][4cc] = 5760, ws: [tap][cc][40] = 2880 -> 8640/buf
// ---------------------------------------------------------------------------
#define BUFF 8640
#define PLANE 1440
#define IMGS 2880

__global__ __launch_bounds__(256, 2) void conv_kernel(float* __restrict__ out) {
    extern __shared__ float sm[];
    const int n0 = blockIdx.z * 2;
    const int x0 = blockIdx.x * 16;
    const int y0 = blockIdx.y * 16;
    const int tid = threadIdx.x;
    const int lane = tid & 31;
    const int wid = tid >> 5;
    const int g = lane >> 2;
    const int t = lane & 3;

    uint32_t smbase;
    asm("{ .reg .u64 tt; cvta.to.shared.u64 tt, %1; cvt.u32.u64 %0, tt; }"
        : "=r"(smbase) : "l"(sm));
    const int laneoff = (lane >> 4) * PLANE + (lane & 15) * 4;   // floats

    float acc[2][2][4][4];
    #pragma unroll
    for (int a = 0; a < 2; ++a)
        #pragma unroll
        for (int b = 0; b < 2; ++b)
            #pragma unroll
            for (int c = 0; c < 4; ++c)
                #pragma unroll
                for (int d = 0; d < 4; ++d) acc[a][b][c][d] = 0.0f;

    // ---- prefetch helper (16B granules)
    auto prefetch = [&](int ch, int buf) {
        uint32_t base = smbase + (uint32_t)buf * BUFF * 4u;
        for (int i = tid; i < 1296; i += 256) {
            int img = i / 648;
            int rem = i - img * 648;
            int plane = rem & 1;
            int pos = rem >> 1;
            int r = pos / 18;
            int c = pos - r * 18;
            int gy = y0 - 1 + r, gx = x0 - 1 + c;
            int ok = ((unsigned)gy < 192u) & ((unsigned)gx < 192u);
            int cgy = ok ? gy : 0, cgx = ok ? gx : 0;
            const float* src = &g_scratch[(((size_t)(n0 + img) * HH + cgy) * WW + cgx) * GC96
                                          + ch * 8 + plane * 4];
            uint32_t dst = base + (uint32_t)(img * IMGS + plane * PLANE + r * 80 + c * 4) * 4u;
            cp16(dst, src, ok ? 16 : 0);
        }
        const float* wsrc = w_prep + ch * 2880;
        uint32_t wdst = base + 5760u * 4u;
        for (int i = tid; i < 720; i += 256)
            cp16(wdst + (uint32_t)i * 16u, wsrc + i * 4, 16);
    };

    prefetch(0, 0);
    CP_COMMIT();

    for (int ch = 0; ch < 12; ++ch) {
        if (ch < 11) {
            prefetch(ch + 1, (ch + 1) & 1);
            CP_COMMIT();
            CP_WAIT(1);
        } else {
            CP_WAIT(0);
        }
        __syncthreads();

        const int bb = ch & 1;
        const float* wsb = sm + bb * BUFF + 5760;
        const uint32_t abase = smbase + (uint32_t)(bb * BUFF + laneoff) * 4u;

        #pragma unroll
        for (int kh = 0; kh < 3; ++kh) {
            #pragma unroll
            for (int kw = 0; kw < 3; ++kw) {
                const int tap = kh * 3 + kw;
                unsigned b0[4], b1[4];
                #pragma unroll
                for (int nc = 0; nc < 4; ++nc) {
                    b0[nc] = __float_as_uint(wsb[tap * 320 + t * 40 + 8 * nc + g]);
                    b1[nc] = __float_as_uint(wsb[tap * 320 + (t + 4) * 40 + 8 * nc + g]);
                }
                #pragma unroll
                for (int img = 0; img < 2; ++img) {
                    #pragma unroll
                    for (int mrow = 0; mrow < 2; ++mrow) {
                        uint32_t addr = abase +
                            (uint32_t)(img * IMGS + (2 * wid + mrow + kh) * 80 + kw * 4) * 4u;
                        unsigned a0, a1, a2, a3;
                        asm volatile("ldmatrix.sync.aligned.m8n8.x4.shared.b16 "
                                     "{%0,%1,%2,%3}, [%4];"
                                     : "=r"(a0), "=r"(a1), "=r"(a2), "=r"(a3)
                                     : "r"(addr));
                        #pragma unroll
                        for (int nc = 0; nc < 4; ++nc)
                            mma_tf32(acc[img][mrow][nc], a0, a1, a2, a3, b0[nc], b1[nc]);
                    }
                }
            }
        }
        __syncthreads();
    }

    // ---- epilogue: + basis0 bias, * gate scale
    #pragma unroll
    for (int img = 0; img < 2; ++img) {
        const float s = s_scale_s[n0 + img];
        #pragma unroll
        for (int mrow = 0; mrow < 2; ++mrow) {
            const int y = y0 + 2 * wid + mrow;
            const int ry = (y == 0) ? 0 : ((y == HH - 1) ? 2 : 1);
            #pragma unroll
            for (int nc = 0; nc < 4; ++nc) {
                #pragma unroll
                for (int e = 0; e < 4; ++e) {
                    const int px = g + ((e >= 2) ? 8 : 0);
                    const int oc = 8 * nc + 2 * t + (e & 1);
                    const int xx = x0 + px;
                    const int cx = (xx == 0) ? 0 : ((xx == WW - 1) ? 2 : 1);
                    out[((size_t)((n0 + img) * CI + oc) * HH + y) * WW + xx] =
                        (acc[img][mrow][nc][e] + bias_g[(ry * 3 + cx) * CI + oc]) * s;
                }
            }
        }
    }
}

// ---------------------------------------------------------------------------
extern "C" void kernel_launch(void* const* d_in, const int* in_sizes, int n_in,
                              void* d_out, int out_size) {
    const float* x  = (const float*)d_in[0];
    const float* wg = (const float*)d_in[1];
    const float* W  = (const float*)d_in[2];
    const float* bw = (const float*)d_in[3];
    float* out = (float*)d_out;
    const int loss_idx = out_size - 1;

    cudaFuncSetAttribute(conv_kernel, cudaFuncAttributeMaxDynamicSharedMemorySize,
                         BUFF * 2 * 4);

    zero_kernel<<<1, 512>>>();
    prep_kernel<<<109, 256>>>(W);
    basis_kernel<<<dim3(3, 192, 16), 256>>>(x, bw, wg, out, loss_idx);
    conv_kernel<<<dim3(12, 12, 8), 256, BUFF * 2 * 4>>>(out);
}

// round 7
// speedup vs baseline: 1.8113x; 1.0148x over previous
#include <cuda_runtime.h>
#include <cstdint>

// ---------------------------------------------------------------------------
// KAGNMoE round 6: conv unchanged (221us, tensor 48.5%); basis kernel
// re-vectorized (float4 smem-staged coalesced stores) to kill the ~400us
// scalar-LSU regression introduced in round 4.
// ---------------------------------------------------------------------------

#define NB 16
#define CI 32
#define HH 192
#define WW 192
#define HW (HH * WW)
#define GC96 96
#define NE 8

// channel-last basis scratch: [n][h][w][96] (tf32-rounded), ~226 MB
__device__ float g_scratch[(size_t)NB * HH * WW * GC96];
__device__ float w_prep[12 * 9 * 8 * 40];   // [chunk][tap][cc][40] tf32
__device__ float gate_acc[NB * CI];
__device__ float gate_mean_s[NB * CI];
__device__ float s_scale_s[NB];
__device__ float bias_g[9 * CI];
__device__ unsigned int blk_ctr;

__device__ __forceinline__ float silu_f(float v) { return v / (1.0f + expf(-v)); }
__device__ __forceinline__ float to_tf32(float v) {
    float r; asm("cvt.rna.tf32.f32 %0, %1;" : "=f"(r) : "f"(v)); return r;
}
__device__ __forceinline__ void mma_tf32(float* d, unsigned a0, unsigned a1,
                                         unsigned a2, unsigned a3,
                                         unsigned b0, unsigned b1) {
    asm("mma.sync.aligned.m16n8k8.row.col.f32.tf32.tf32.f32 "
        "{%0,%1,%2,%3}, {%4,%5,%6,%7}, {%8,%9}, {%0,%1,%2,%3};"
        : "+f"(d[0]), "+f"(d[1]), "+f"(d[2]), "+f"(d[3])
        : "r"(a0), "r"(a1), "r"(a2), "r"(a3), "r"(b0), "r"(b1));
}
__device__ __forceinline__ void cp16(uint32_t dst, const void* src, int sz) {
    asm volatile("cp.async.ca.shared.global [%0], [%1], 16, %2;"
                 :: "r"(dst), "l"(src), "r"(sz));
}
#define CP_COMMIT() asm volatile("cp.async.commit_group;")
#define CP_WAIT(n)  asm volatile("cp.async.wait_group %0;" :: "n"(n))

// ---------------------------------------------------------------------------
// K0: zero gate accumulators + counter (graph-replay determinism)
// ---------------------------------------------------------------------------
__global__ void zero_kernel() {
    gate_acc[threadIdx.x] = 0.0f;
    if (threadIdx.x == 0) blk_ctr = 0u;
}

// ---------------------------------------------------------------------------
// K1: weight prep (tf32, [chunk][tap][cc][40]) + basis-0 bias (last block)
// ---------------------------------------------------------------------------
__global__ void prep_kernel(const float* __restrict__ W) {
    if (blockIdx.x < 108) {
        int j = blockIdx.x * 256 + threadIdx.x;    // < 27648
        int ch = j / (9 * 8 * 32);
        int r0 = j - ch * (9 * 8 * 32);
        int tap = r0 / 256;
        int r1 = r0 - tap * 256;
        int cc = r1 >> 5;
        int oc = r1 & 31;
        float w = W[((size_t)oc * 128 + 32 + ch * 8 + cc) * 9 + tap];
        w_prep[((ch * 9 + tap) * 8 + cc) * 40 + oc] = to_tf32(w);
        return;
    }
    int oc = threadIdx.x;
    if (oc >= 32) return;
    float S[9];
    #pragma unroll
    for (int k = 0; k < 9; ++k) S[k] = 0.0f;
    for (int ci = 0; ci < 32; ++ci)
        #pragma unroll
        for (int k = 0; k < 9; ++k)
            S[k] += W[((size_t)oc * 128 + ci) * 9 + k];
    const float c0 = silu_f(1.0f);
    #pragma unroll
    for (int ry = 0; ry < 3; ++ry)
        #pragma unroll
        for (int cx = 0; cx < 3; ++cx) {
            float b = 0.0f;
            #pragma unroll
            for (int kh = 0; kh < 3; ++kh) {
                if ((ry == 0 && kh == 0) || (ry == 2 && kh == 2)) continue;
                #pragma unroll
                for (int kw = 0; kw < 3; ++kw) {
                    if ((cx == 0 && kw == 0) || (cx == 2 && kw == 2)) continue;
                    b += S[kh * 3 + kw];
                }
            }
            bias_g[(ry * 3 + cx) * CI + oc] = b * c0;
        }
}

// ---------------------------------------------------------------------------
// K2: basis (channel-last, tf32) + gate partial sums; last block: gating+loss
// grid (3, 192, 16): (w-chunk of 64, h, n). 256 threads = 4 ci-sub x 64 px.
// smem st[64 px][100] (pad 100: float4 rows; read side conflict-free),
// drained as 6 LDS.128 + 6 coalesced STG.128 per thread.
// ---------------------------------------------------------------------------
__device__ float cv_sq(const float* v) {
    float m = 0.0f;
    #pragma unroll
    for (int i = 0; i < NE; ++i) m += v[i];
    m *= (1.0f / NE);
    float var = 0.0f;
    #pragma unroll
    for (int i = 0; i < NE; ++i) { float d = v[i] - m; var += d * d; }
    var *= (1.0f / (NE - 1));
    return var / (m * m + 1e-10f);
}

__global__ __launch_bounds__(256) void basis_kernel(const float* __restrict__ x,
                                                    const float* __restrict__ bw,
                                                    const float* __restrict__ wg,
                                                    float* __restrict__ d_out,
                                                    int loss_idx) {
    const int n = blockIdx.z, h = blockIdx.y, w0 = blockIdx.x * 64;
    const int tid = threadIdx.x;
    const int cisub = tid >> 6;
    const int pix = tid & 63;

    __shared__ __align__(16) float st[64 * 100];
    const float beta2 = 2.25f * bw[1];
    const float beta3 = (300.0f / 9.0f) * bw[2];

    #pragma unroll
    for (int it = 0; it < 8; ++it) {
        const int ci = it * 4 + cisub;
        float v = x[((size_t)(n * CI + ci) * HH + h) * WW + w0 + pix];
        // gate partial: warp = fixed ci, 32 consecutive pixels
        float ws = v;
        #pragma unroll
        for (int o = 16; o > 0; o >>= 1) ws += __shfl_down_sync(0xffffffffu, ws, o);
        if ((tid & 31) == 0) atomicAdd(&gate_acc[n * CI + ci], ws);
        float t = tanhf(v);
        float p2 = t * t - beta2;
        float p3 = t * p2 - beta3 * t;
        st[pix * 100 + ci]      = to_tf32(silu_f(t));
        st[pix * 100 + 32 + ci] = to_tf32(silu_f(p2));
        st[pix * 100 + 64 + ci] = to_tf32(silu_f(p3));
    }
    __syncthreads();

    // coalesced float4 drain: 64 px * 24 float4 = 1536 float4
    float4* gout4 = reinterpret_cast<float4*>(
        g_scratch + ((size_t)(n * HH + h) * WW + w0) * GC96);
    const float4* st4 = reinterpret_cast<const float4*>(st);
    #pragma unroll
    for (int it = 0; it < 6; ++it) {
        int f4 = it * 256 + tid;
        int p = f4 / 24, c4 = f4 - p * 24;
        gout4[f4] = st4[p * 25 + c4];
    }

    // ---- last block: finalize means + gating + loss
    __shared__ unsigned int s_last;
    __threadfence();
    __syncthreads();
    if (tid == 0) s_last = atomicAdd(&blk_ctr, 1u);
    __syncthreads();
    if (s_last != 3u * 192u * 16u - 1u) return;
    __threadfence();
    gate_mean_s[tid] = gate_acc[tid] * (1.0f / 36864.0f);
    gate_mean_s[tid + 256] = gate_acc[tid + 256] * (1.0f / 36864.0f);
    __syncthreads();

    __shared__ float sg0[NB], sg1[NB];
    __shared__ int si0[NB], si1[NB];
    if (tid < NB) {
        float l[NE];
        #pragma unroll
        for (int e = 0; e < NE; ++e) {
            float a = 0.0f;
            #pragma unroll
            for (int c = 0; c < CI; ++c) a += gate_mean_s[tid * CI + c] * wg[c * NE + e];
            l[e] = a;
        }
        float m = l[0];
        #pragma unroll
        for (int e = 1; e < NE; ++e) m = fmaxf(m, l[e]);
        float p[NE]; float sum = 0.0f;
        #pragma unroll
        for (int e = 0; e < NE; ++e) { p[e] = expf(l[e] - m); sum += p[e]; }
        float inv = 1.0f / sum;
        #pragma unroll
        for (int e = 0; e < NE; ++e) p[e] *= inv;
        int i0 = 0; float v0 = p[0];
        #pragma unroll
        for (int e = 1; e < NE; ++e) if (p[e] > v0) { v0 = p[e]; i0 = e; }
        int i1 = -1; float v1 = -1.0f;
        #pragma unroll
        for (int e = 0; e < NE; ++e) if (e != i0 && p[e] > v1) { v1 = p[e]; i1 = e; }
        float invS = 1.0f / (v0 + v1 + 1e-6f);
        sg0[tid] = v0 * invS; sg1[tid] = v1 * invS;
        si0[tid] = i0; si1[tid] = i1;
        s_scale_s[tid] = (v0 + v1) * invS;
    }
    __syncthreads();
    if (tid == 0) {
        float imp[NE] = {0}, ld[NE] = {0};
        for (int b = 0; b < NB; ++b) {
            imp[si0[b]] += sg0[b]; imp[si1[b]] += sg1[b];
            ld[si0[b]] += 1.0f;    ld[si1[b]] += 1.0f;
        }
        d_out[loss_idx] = 0.01f * (cv_sq(imp) + cv_sq(ld));
    }
}

// ---------------------------------------------------------------------------
// K3: conv via mma m16n8k8 tf32, ldmatrix A-frags, cp.async double buffer.
// (unchanged from round 5: 221us, tensor 48.5%)
// ---------------------------------------------------------------------------
#define BUFF 8640
#define PLANE 1440
#define IMGS 2880

__global__ __launch_bounds__(256, 2) void conv_kernel(float* __restrict__ out) {
    extern __shared__ float sm[];
    const int n0 = blockIdx.z * 2;
    const int x0 = blockIdx.x * 16;
    const int y0 = blockIdx.y * 16;
    const int tid = threadIdx.x;
    const int lane = tid & 31;
    const int wid = tid >> 5;
    const int g = lane >> 2;
    const int t = lane & 3;

    uint32_t smbase;
    asm("{ .reg .u64 tt; cvta.to.shared.u64 tt, %1; cvt.u32.u64 %0, tt; }"
        : "=r"(smbase) : "l"(sm));
    const int laneoff = (lane >> 4) * PLANE + (lane & 15) * 4;   // floats

    float acc[2][2][4][4];
    #pragma unroll
    for (int a = 0; a < 2; ++a)
        #pragma unroll
        for (int b = 0; b < 2; ++b)
            #pragma unroll
            for (int c = 0; c < 4; ++c)
                #pragma unroll
                for (int d = 0; d < 4; ++d) acc[a][b][c][d] = 0.0f;

    // ---- prefetch helper (16B granules)
    auto prefetch = [&](int ch, int buf) {
        uint32_t base = smbase + (uint32_t)buf * BUFF * 4u;
        for (int i = tid; i < 1296; i += 256) {
            int img = i / 648;
            int rem = i - img * 648;
            int plane = rem & 1;
            int pos = rem >> 1;
            int r = pos / 18;
            int c = pos - r * 18;
            int gy = y0 - 1 + r, gx = x0 - 1 + c;
            int ok = ((unsigned)gy < 192u) & ((unsigned)gx < 192u);
            int cgy = ok ? gy : 0, cgx = ok ? gx : 0;
            const float* src = &g_scratch[(((size_t)(n0 + img) * HH + cgy) * WW + cgx) * GC96
                                          + ch * 8 + plane * 4];
            uint32_t dst = base + (uint32_t)(img * IMGS + plane * PLANE + r * 80 + c * 4) * 4u;
            cp16(dst, src, ok ? 16 : 0);
        }
        const float* wsrc = w_prep + ch * 2880;
        uint32_t wdst = base + 5760u * 4u;
        for (int i = tid; i < 720; i += 256)
            cp16(wdst + (uint32_t)i * 16u, wsrc + i * 4, 16);
    };

    prefetch(0, 0);
    CP_COMMIT();

    for (int ch = 0; ch < 12; ++ch) {
        if (ch < 11) {
            prefetch(ch + 1, (ch + 1) & 1);
            CP_COMMIT();
            CP_WAIT(1);
        } else {
            CP_WAIT(0);
        }
        __syncthreads();

        const int bb = ch & 1;
        const float* wsb = sm + bb * BUFF + 5760;
        const uint32_t abase = smbase + (uint32_t)(bb * BUFF + laneoff) * 4u;

        #pragma unroll
        for (int kh = 0; kh < 3; ++kh) {
            #pragma unroll
            for (int kw = 0; kw < 3; ++kw) {
                const int tap = kh * 3 + kw;
                unsigned b0[4], b1[4];
                #pragma unroll
                for (int nc = 0; nc < 4; ++nc) {
                    b0[nc] = __float_as_uint(wsb[tap * 320 + t * 40 + 8 * nc + g]);
                    b1[nc] = __float_as_uint(wsb[tap * 320 + (t + 4) * 40 + 8 * nc + g]);
                }
                #pragma unroll
                for (int img = 0; img < 2; ++img) {
                    #pragma unroll
                    for (int mrow = 0; mrow < 2; ++mrow) {
                        uint32_t addr = abase +
                            (uint32_t)(img * IMGS + (2 * wid + mrow + kh) * 80 + kw * 4) * 4u;
                        unsigned a0, a1, a2, a3;
                        asm volatile("ldmatrix.sync.aligned.m8n8.x4.shared.b16 "
                                     "{%0,%1,%2,%3}, [%4];"
                                     : "=r"(a0), "=r"(a1), "=r"(a2), "=r"(a3)
                                     : "r"(addr));
                        #pragma unroll
                        for (int nc = 0; nc < 4; ++nc)
                            mma_tf32(acc[img][mrow][nc], a0, a1, a2, a3, b0[nc], b1[nc]);
                    }
                }
            }
        }
        __syncthreads();
    }

    // ---- epilogue: + basis0 bias, * gate scale
    #pragma unroll
    for (int img = 0; img < 2; ++img) {
        const float s = s_scale_s[n0 + img];
        #pragma unroll
        for (int mrow = 0; mrow < 2; ++mrow) {
            const int y = y0 + 2 * wid + mrow;
            const int ry = (y == 0) ? 0 : ((y == HH - 1) ? 2 : 1);
            #pragma unroll
            for (int nc = 0; nc < 4; ++nc) {
                #pragma unroll
                for (int e = 0; e < 4; ++e) {
                    const int px = g + ((e >= 2) ? 8 : 0);
                    const int oc = 8 * nc + 2 * t + (e & 1);
                    const int xx = x0 + px;
                    const int cx = (xx == 0) ? 0 : ((xx == WW - 1) ? 2 : 1);
                    out[((size_t)((n0 + img) * CI + oc) * HH + y) * WW + xx] =
                        (acc[img][mrow][nc][e] + bias_g[(ry * 3 + cx) * CI + oc]) * s;
                }
            }
        }
    }
}

// ---------------------------------------------------------------------------
extern "C" void kernel_launch(void* const* d_in, const int* in_sizes, int n_in,
                              void* d_out, int out_size) {
    const float* x  = (const float*)d_in[0];
    const float* wg = (const float*)d_in[1];
    const float* W  = (const float*)d_in[2];
    const float* bw = (const float*)d_in[3];
    float* out = (float*)d_out;
    const int loss_idx = out_size - 1;

    cudaFuncSetAttribute(conv_kernel, cudaFuncAttributeMaxDynamicSharedMemorySize,
                         BUFF * 2 * 4);

    zero_kernel<<<1, 512>>>();
    prep_kernel<<<109, 256>>>(W);
    basis_kernel<<<dim3(3, 192, 16), 256>>>(x, bw, wg, out, loss_idx);
    conv_kernel<<<dim3(12, 12, 8), 256, BUFF * 2 * 4>>>(out);
}

// round 8
// speedup vs baseline: 3.3959x; 1.8749x over previous
#include <cuda_runtime.h>
#include <cstdint>

// ---------------------------------------------------------------------------
// KAGNMoE round 7: conv unchanged (219.7us). Basis stripped to a pure
// transform (no fences / atomics / shuffles -- the R4 fused-gating machinery
// was the ~420us regression). Gating restored to the R1/R2 standalone
// kernels; gate_mean runs first to leave x L2-resident for basis.
// ---------------------------------------------------------------------------

#define NB 16
#define CI 32
#define HH 192
#define WW 192
#define HW (HH * WW)
#define GC96 96
#define NE 8

// channel-last basis scratch: [n][h][w][96] (tf32-rounded), ~226 MB
__device__ float g_scratch[(size_t)NB * HH * WW * GC96];
__device__ float w_prep[12 * 9 * 8 * 40];   // [chunk][tap][cc][40] tf32
__device__ float gate_mean_s[NB * CI];
__device__ float s_scale_s[NB];
__device__ float bias_g[9 * CI];

__device__ __forceinline__ float silu_f(float v) { return v / (1.0f + expf(-v)); }
__device__ __forceinline__ float to_tf32(float v) {
    float r; asm("cvt.rna.tf32.f32 %0, %1;" : "=f"(r) : "f"(v)); return r;
}
__device__ __forceinline__ void mma_tf32(float* d, unsigned a0, unsigned a1,
                                         unsigned a2, unsigned a3,
                                         unsigned b0, unsigned b1) {
    asm("mma.sync.aligned.m16n8k8.row.col.f32.tf32.tf32.f32 "
        "{%0,%1,%2,%3}, {%4,%5,%6,%7}, {%8,%9}, {%0,%1,%2,%3};"
        : "+f"(d[0]), "+f"(d[1]), "+f"(d[2]), "+f"(d[3])
        : "r"(a0), "r"(a1), "r"(a2), "r"(a3), "r"(b0), "r"(b1));
}
__device__ __forceinline__ void cp16(uint32_t dst, const void* src, int sz) {
    asm volatile("cp.async.ca.shared.global [%0], [%1], 16, %2;"
                 :: "r"(dst), "l"(src), "r"(sz));
}
#define CP_COMMIT() asm volatile("cp.async.commit_group;")
#define CP_WAIT(n)  asm volatile("cp.async.wait_group %0;" :: "n"(n))

// ---------------------------------------------------------------------------
// K0: weight prep (tf32, [chunk][tap][cc][40]) + basis-0 bias (last block)
// ---------------------------------------------------------------------------
__global__ void prep_kernel(const float* __restrict__ W) {
    if (blockIdx.x < 108) {
        int j = blockIdx.x * 256 + threadIdx.x;    // < 27648
        int ch = j / (9 * 8 * 32);
        int r0 = j - ch * (9 * 8 * 32);
        int tap = r0 / 256;
        int r1 = r0 - tap * 256;
        int cc = r1 >> 5;
        int oc = r1 & 31;
        float w = W[((size_t)oc * 128 + 32 + ch * 8 + cc) * 9 + tap];
        w_prep[((ch * 9 + tap) * 8 + cc) * 40 + oc] = to_tf32(w);
        return;
    }
    int oc = threadIdx.x;
    if (oc >= 32) return;
    float S[9];
    #pragma unroll
    for (int k = 0; k < 9; ++k) S[k] = 0.0f;
    for (int ci = 0; ci < 32; ++ci)
        #pragma unroll
        for (int k = 0; k < 9; ++k)
            S[k] += W[((size_t)oc * 128 + ci) * 9 + k];
    const float c0 = silu_f(1.0f);
    #pragma unroll
    for (int ry = 0; ry < 3; ++ry)
        #pragma unroll
        for (int cx = 0; cx < 3; ++cx) {
            float b = 0.0f;
            #pragma unroll
            for (int kh = 0; kh < 3; ++kh) {
                if ((ry == 0 && kh == 0) || (ry == 2 && kh == 2)) continue;
                #pragma unroll
                for (int kw = 0; kw < 3; ++kw) {
                    if ((cx == 0 && kw == 0) || (cx == 2 && kw == 2)) continue;
                    b += S[kh * 3 + kw];
                }
            }
            bias_g[(ry * 3 + cx) * CI + oc] = b * c0;
        }
}

// ---------------------------------------------------------------------------
// K1: per-(n,ci) spatial mean of x (R1 version, proven fast)
// ---------------------------------------------------------------------------
__global__ void gate_mean_kernel(const float* __restrict__ x) {
    const int b = blockIdx.x;                 // n*32 + ci (512 blocks)
    const float* xp = x + (size_t)b * HW;
    float s = 0.0f;
    for (int i = threadIdx.x; i < HW; i += 256) s += xp[i];
    __shared__ float sh[8];
    #pragma unroll
    for (int o = 16; o > 0; o >>= 1) s += __shfl_down_sync(0xffffffffu, s, o);
    if ((threadIdx.x & 31) == 0) sh[threadIdx.x >> 5] = s;
    __syncthreads();
    if (threadIdx.x < 8) {
        s = sh[threadIdx.x];
        #pragma unroll
        for (int o = 4; o > 0; o >>= 1) s += __shfl_down_sync(0xffu, s, o);
        if (threadIdx.x == 0) gate_mean_s[b] = s * (1.0f / 36864.0f);
    }
}

// ---------------------------------------------------------------------------
// K2: gating (R1/R2 version, ~11us measured)
// ---------------------------------------------------------------------------
__device__ float cv_sq(const float* v) {
    float m = 0.0f;
    #pragma unroll
    for (int i = 0; i < NE; ++i) m += v[i];
    m *= (1.0f / NE);
    float var = 0.0f;
    #pragma unroll
    for (int i = 0; i < NE; ++i) { float d = v[i] - m; var += d * d; }
    var *= (1.0f / (NE - 1));
    return var / (m * m + 1e-10f);
}

__global__ void gating_kernel(const float* __restrict__ wg,
                              float* __restrict__ d_out, int loss_idx) {
    __shared__ float sg0[NB], sg1[NB];
    __shared__ int si0[NB], si1[NB];
    int t = threadIdx.x;
    if (t < NB) {
        float l[NE];
        #pragma unroll
        for (int e = 0; e < NE; ++e) {
            float a = 0.0f;
            #pragma unroll
            for (int c = 0; c < CI; ++c) a += gate_mean_s[t * CI + c] * wg[c * NE + e];
            l[e] = a;
        }
        float m = l[0];
        #pragma unroll
        for (int e = 1; e < NE; ++e) m = fmaxf(m, l[e]);
        float p[NE]; float sum = 0.0f;
        #pragma unroll
        for (int e = 0; e < NE; ++e) { p[e] = expf(l[e] - m); sum += p[e]; }
        float inv = 1.0f / sum;
        #pragma unroll
        for (int e = 0; e < NE; ++e) p[e] *= inv;
        int i0 = 0; float v0 = p[0];
        #pragma unroll
        for (int e = 1; e < NE; ++e) if (p[e] > v0) { v0 = p[e]; i0 = e; }
        int i1 = -1; float v1 = -1.0f;
        #pragma unroll
        for (int e = 0; e < NE; ++e) if (e != i0 && p[e] > v1) { v1 = p[e]; i1 = e; }
        float invS = 1.0f / (v0 + v1 + 1e-6f);
        sg0[t] = v0 * invS;
        sg1[t] = v1 * invS;
        si0[t] = i0;
        si1[t] = i1;
        s_scale_s[t] = (v0 + v1) * invS;
    }
    __syncthreads();
    if (t == 0) {
        float imp[NE] = {0}, ld[NE] = {0};
        for (int n = 0; n < NB; ++n) {
            imp[si0[n]] += sg0[n];
            imp[si1[n]] += sg1[n];
            ld[si0[n]] += 1.0f;
            ld[si1[n]] += 1.0f;
        }
        d_out[loss_idx] = 0.01f * (cv_sq(imp) + cv_sq(ld));
    }
}

// ---------------------------------------------------------------------------
// K3: basis, pure transform. grid (3,192,16); 256 thr = 4 ci-sub x 64 px.
// 8 coalesced scalar loads + identical math + smem transpose + float4 drain.
// NO atomics / fences / shuffles.
// ---------------------------------------------------------------------------
__global__ __launch_bounds__(256) void basis_kernel(const float* __restrict__ x,
                                                    const float* __restrict__ bw) {
    const int n = blockIdx.z, h = blockIdx.y, w0 = blockIdx.x * 64;
    const int tid = threadIdx.x;
    const int cisub = tid >> 6;
    const int pix = tid & 63;

    __shared__ __align__(16) float st[64 * 100];
    const float beta2 = 2.25f * bw[1];
    const float beta3 = (300.0f / 9.0f) * bw[2];

    #pragma unroll
    for (int it = 0; it < 8; ++it) {
        const int ci = it * 4 + cisub;
        float v = x[((size_t)(n * CI + ci) * HH + h) * WW + w0 + pix];
        float t = tanhf(v);
        float p2 = t * t - beta2;
        float p3 = t * p2 - beta3 * t;
        st[pix * 100 + ci]      = to_tf32(silu_f(t));
        st[pix * 100 + 32 + ci] = to_tf32(silu_f(p2));
        st[pix * 100 + 64 + ci] = to_tf32(silu_f(p3));
    }
    __syncthreads();

    // coalesced float4 drain: 64 px * 24 float4 = 1536 float4
    float4* gout4 = reinterpret_cast<float4*>(
        g_scratch + ((size_t)(n * HH + h) * WW + w0) * GC96);
    const float4* st4 = reinterpret_cast<const float4*>(st);
    #pragma unroll
    for (int it = 0; it < 6; ++it) {
        int f4 = it * 256 + tid;
        int p = f4 / 24, c4 = f4 - p * 24;
        gout4[f4] = st4[p * 25 + c4];
    }
}

// ---------------------------------------------------------------------------
// K4: conv via mma m16n8k8 tf32, ldmatrix A-frags, cp.async double buffer.
// (byte-identical to round 6/7: 219.7us, tensor 48.6%)
// ---------------------------------------------------------------------------
#define BUFF 8640
#define PLANE 1440
#define IMGS 2880

__global__ __launch_bounds__(256, 2) void conv_kernel(float* __restrict__ out) {
    extern __shared__ float sm[];
    const int n0 = blockIdx.z * 2;
    const int x0 = blockIdx.x * 16;
    const int y0 = blockIdx.y * 16;
    const int tid = threadIdx.x;
    const int lane = tid & 31;
    const int wid = tid >> 5;
    const int g = lane >> 2;
    const int t = lane & 3;

    uint32_t smbase;
    asm("{ .reg .u64 tt; cvta.to.shared.u64 tt, %1; cvt.u32.u64 %0, tt; }"
        : "=r"(smbase) : "l"(sm));
    const int laneoff = (lane >> 4) * PLANE + (lane & 15) * 4;   // floats

    float acc[2][2][4][4];
    #pragma unroll
    for (int a = 0; a < 2; ++a)
        #pragma unroll
        for (int b = 0; b < 2; ++b)
            #pragma unroll
            for (int c = 0; c < 4; ++c)
                #pragma unroll
                for (int d = 0; d < 4; ++d) acc[a][b][c][d] = 0.0f;

    // ---- prefetch helper (16B granules)
    auto prefetch = [&](int ch, int buf) {
        uint32_t base = smbase + (uint32_t)buf * BUFF * 4u;
        for (int i = tid; i < 1296; i += 256) {
            int img = i / 648;
            int rem = i - img * 648;
            int plane = rem & 1;
            int pos = rem >> 1;
            int r = pos / 18;
            int c = pos - r * 18;
            int gy = y0 - 1 + r, gx = x0 - 1 + c;
            int ok = ((unsigned)gy < 192u) & ((unsigned)gx < 192u);
            int cgy = ok ? gy : 0, cgx = ok ? gx : 0;
            const float* src = &g_scratch[(((size_t)(n0 + img) * HH + cgy) * WW + cgx) * GC96
                                          + ch * 8 + plane * 4];
            uint32_t dst = base + (uint32_t)(img * IMGS + plane * PLANE + r * 80 + c * 4) * 4u;
            cp16(dst, src, ok ? 16 : 0);
        }
        const float* wsrc = w_prep + ch * 2880;
        uint32_t wdst = base + 5760u * 4u;
        for (int i = tid; i < 720; i += 256)
            cp16(wdst + (uint32_t)i * 16u, wsrc + i * 4, 16);
    };

    prefetch(0, 0);
    CP_COMMIT();

    for (int ch = 0; ch < 12; ++ch) {
        if (ch < 11) {
            prefetch(ch + 1, (ch + 1) & 1);
            CP_COMMIT();
            CP_WAIT(1);
        } else {
            CP_WAIT(0);
        }
        __syncthreads();

        const int bb = ch & 1;
        const float* wsb = sm + bb * BUFF + 5760;
        const uint32_t abase = smbase + (uint32_t)(bb * BUFF + laneoff) * 4u;

        #pragma unroll
        for (int kh = 0; kh < 3; ++kh) {
            #pragma unroll
            for (int kw = 0; kw < 3; ++kw) {
                const int tap = kh * 3 + kw;
                unsigned b0[4], b1[4];
                #pragma unroll
                for (int nc = 0; nc < 4; ++nc) {
                    b0[nc] = __float_as_uint(wsb[tap * 320 + t * 40 + 8 * nc + g]);
                    b1[nc] = __float_as_uint(wsb[tap * 320 + (t + 4) * 40 + 8 * nc + g]);
                }
                #pragma unroll
                for (int img = 0; img < 2; ++img) {
                    #pragma unroll
                    for (int mrow = 0; mrow < 2; ++mrow) {
                        uint32_t addr = abase +
                            (uint32_t)(img * IMGS + (2 * wid + mrow + kh) * 80 + kw * 4) * 4u;
                        unsigned a0, a1, a2, a3;
                        asm volatile("ldmatrix.sync.aligned.m8n8.x4.shared.b16 "
                                     "{%0,%1,%2,%3}, [%4];"
                                     : "=r"(a0), "=r"(a1), "=r"(a2), "=r"(a3)
                                     : "r"(addr));
                        #pragma unroll
                        for (int nc = 0; nc < 4; ++nc)
                            mma_tf32(acc[img][mrow][nc], a0, a1, a2, a3, b0[nc], b1[nc]);
                    }
                }
            }
        }
        __syncthreads();
    }

    // ---- epilogue: + basis0 bias, * gate scale
    #pragma unroll
    for (int img = 0; img < 2; ++img) {
        const float s = s_scale_s[n0 + img];
        #pragma unroll
        for (int mrow = 0; mrow < 2; ++mrow) {
            const int y = y0 + 2 * wid + mrow;
            const int ry = (y == 0) ? 0 : ((y == HH - 1) ? 2 : 1);
            #pragma unroll
            for (int nc = 0; nc < 4; ++nc) {
                #pragma unroll
                for (int e = 0; e < 4; ++e) {
                    const int px = g + ((e >= 2) ? 8 : 0);
                    const int oc = 8 * nc + 2 * t + (e & 1);
                    const int xx = x0 + px;
                    const int cx = (xx == 0) ? 0 : ((xx == WW - 1) ? 2 : 1);
                    out[((size_t)((n0 + img) * CI + oc) * HH + y) * WW + xx] =
                        (acc[img][mrow][nc][e] + bias_g[(ry * 3 + cx) * CI + oc]) * s;
                }
            }
        }
    }
}

// ---------------------------------------------------------------------------
extern "C" void kernel_launch(void* const* d_in, const int* in_sizes, int n_in,
                              void* d_out, int out_size) {
    const float* x  = (const float*)d_in[0];
    const float* wg = (const float*)d_in[1];
    const float* W  = (const float*)d_in[2];
    const float* bw = (const float*)d_in[3];
    float* out = (float*)d_out;
    const int loss_idx = out_size - 1;

    cudaFuncSetAttribute(conv_kernel, cudaFuncAttributeMaxDynamicSharedMemorySize,
                         BUFF * 2 * 4);

    gate_mean_kernel<<<NB * CI, 256>>>(x);       // warms L2 with x for basis
    gating_kernel<<<1, 32>>>(wg, out, loss_idx);
    prep_kernel<<<109, 256>>>(W);
    basis_kernel<<<dim3(3, 192, 16), 256>>>(x, bw);
    conv_kernel<<<dim3(12, 12, 8), 256, BUFF * 2 * 4>>>(out);
}

// round 9
// speedup vs baseline: 3.5665x; 1.0502x over previous
#include <cuda_runtime.h>
#include <cstdint>

// ---------------------------------------------------------------------------
// KAGNMoE round 8: conv B-fragments now via ldmatrix.x4 (weight tile stored
// as 8n x 4k b32 matrices) -- replaces 72 scalar LDS/chunk with 18 LDSM.
// Everything else unchanged from round 7 (344.5us total, conv 220us).
// ---------------------------------------------------------------------------

#define NB 16
#define CI 32
#define HH 192
#define WW 192
#define HW (HH * WW)
#define GC96 96
#define NE 8

// channel-last basis scratch: [n][h][w][96] (tf32-rounded), ~226 MB
__device__ float g_scratch[(size_t)NB * HH * WW * GC96];
// weights: [ch][tap][p(2)][m(4)][n(8)][k'(4)] tf32, 2304 floats per chunk
__device__ float w_prep[12 * 2304];
__device__ float gate_mean_s[NB * CI];
__device__ float s_scale_s[NB];
__device__ float bias_g[9 * CI];

__device__ __forceinline__ float silu_f(float v) { return v / (1.0f + expf(-v)); }
__device__ __forceinline__ float to_tf32(float v) {
    float r; asm("cvt.rna.tf32.f32 %0, %1;" : "=f"(r) : "f"(v)); return r;
}
__device__ __forceinline__ void mma_tf32(float* d, unsigned a0, unsigned a1,
                                         unsigned a2, unsigned a3,
                                         unsigned b0, unsigned b1) {
    asm("mma.sync.aligned.m16n8k8.row.col.f32.tf32.tf32.f32 "
        "{%0,%1,%2,%3}, {%4,%5,%6,%7}, {%8,%9}, {%0,%1,%2,%3};"
        : "+f"(d[0]), "+f"(d[1]), "+f"(d[2]), "+f"(d[3])
        : "r"(a0), "r"(a1), "r"(a2), "r"(a3), "r"(b0), "r"(b1));
}
__device__ __forceinline__ void cp16(uint32_t dst, const void* src, int sz) {
    asm volatile("cp.async.ca.shared.global [%0], [%1], 16, %2;"
                 :: "r"(dst), "l"(src), "r"(sz));
}
#define CP_COMMIT() asm volatile("cp.async.commit_group;")
#define CP_WAIT(n)  asm volatile("cp.async.wait_group %0;" :: "n"(n))

// ---------------------------------------------------------------------------
// K0: weight prep + basis-0 bias (last block).
// w_prep element j = ((((ch*9+tap)*2+p)*4+m)*8+n)*4+k':
//   nc = 2p + (m>>1), khalf = m&1, cc = khalf*4+k', oc = 8*nc+n
//   value = tf32(W[oc][32 + ch*8 + cc][tap])
// One ldmatrix.x4 at lane*16B then yields {b0[2p],b1[2p],b0[2p+1],b1[2p+1]}.
// ---------------------------------------------------------------------------
__global__ void prep_kernel(const float* __restrict__ W) {
    if (blockIdx.x < 108) {
        int j = blockIdx.x * 256 + threadIdx.x;    // < 27648
        int kp = j & 3;
        int n  = (j >> 2) & 7;
        int m  = (j >> 5) & 3;
        int p  = (j >> 7) & 1;
        int tap = (j >> 8) % 9;
        int ch  = (j >> 8) / 9;
        int nc = 2 * p + (m >> 1);
        int cc = (m & 1) * 4 + kp;
        int oc = 8 * nc + n;
        w_prep[j] = to_tf32(W[((size_t)oc * 128 + 32 + ch * 8 + cc) * 9 + tap]);
        return;
    }
    int oc = threadIdx.x;
    if (oc >= 32) return;
    float S[9];
    #pragma unroll
    for (int k = 0; k < 9; ++k) S[k] = 0.0f;
    for (int ci = 0; ci < 32; ++ci)
        #pragma unroll
        for (int k = 0; k < 9; ++k)
            S[k] += W[((size_t)oc * 128 + ci) * 9 + k];
    const float c0 = silu_f(1.0f);
    #pragma unroll
    for (int ry = 0; ry < 3; ++ry)
        #pragma unroll
        for (int cx = 0; cx < 3; ++cx) {
            float b = 0.0f;
            #pragma unroll
            for (int kh = 0; kh < 3; ++kh) {
                if ((ry == 0 && kh == 0) || (ry == 2 && kh == 2)) continue;
                #pragma unroll
                for (int kw = 0; kw < 3; ++kw) {
                    if ((cx == 0 && kw == 0) || (cx == 2 && kw == 2)) continue;
                    b += S[kh * 3 + kw];
                }
            }
            bias_g[(ry * 3 + cx) * CI + oc] = b * c0;
        }
}

// ---------------------------------------------------------------------------
// K1: per-(n,ci) spatial mean of x
// ---------------------------------------------------------------------------
__global__ void gate_mean_kernel(const float* __restrict__ x) {
    const int b = blockIdx.x;
    const float* xp = x + (size_t)b * HW;
    float s = 0.0f;
    for (int i = threadIdx.x; i < HW; i += 256) s += xp[i];
    __shared__ float sh[8];
    #pragma unroll
    for (int o = 16; o > 0; o >>= 1) s += __shfl_down_sync(0xffffffffu, s, o);
    if ((threadIdx.x & 31) == 0) sh[threadIdx.x >> 5] = s;
    __syncthreads();
    if (threadIdx.x < 8) {
        s = sh[threadIdx.x];
        #pragma unroll
        for (int o = 4; o > 0; o >>= 1) s += __shfl_down_sync(0xffu, s, o);
        if (threadIdx.x == 0) gate_mean_s[b] = s * (1.0f / 36864.0f);
    }
}

// ---------------------------------------------------------------------------
// K2: gating
// ---------------------------------------------------------------------------
__device__ float cv_sq(const float* v) {
    float m = 0.0f;
    #pragma unroll
    for (int i = 0; i < NE; ++i) m += v[i];
    m *= (1.0f / NE);
    float var = 0.0f;
    #pragma unroll
    for (int i = 0; i < NE; ++i) { float d = v[i] - m; var += d * d; }
    var *= (1.0f / (NE - 1));
    return var / (m * m + 1e-10f);
}

__global__ void gating_kernel(const float* __restrict__ wg,
                              float* __restrict__ d_out, int loss_idx) {
    __shared__ float sg0[NB], sg1[NB];
    __shared__ int si0[NB], si1[NB];
    int t = threadIdx.x;
    if (t < NB) {
        float l[NE];
        #pragma unroll
        for (int e = 0; e < NE; ++e) {
            float a = 0.0f;
            #pragma unroll
            for (int c = 0; c < CI; ++c) a += gate_mean_s[t * CI + c] * wg[c * NE + e];
            l[e] = a;
        }
        float m = l[0];
        #pragma unroll
        for (int e = 1; e < NE; ++e) m = fmaxf(m, l[e]);
        float p[NE]; float sum = 0.0f;
        #pragma unroll
        for (int e = 0; e < NE; ++e) { p[e] = expf(l[e] - m); sum += p[e]; }
        float inv = 1.0f / sum;
        #pragma unroll
        for (int e = 0; e < NE; ++e) p[e] *= inv;
        int i0 = 0; float v0 = p[0];
        #pragma unroll
        for (int e = 1; e < NE; ++e) if (p[e] > v0) { v0 = p[e]; i0 = e; }
        int i1 = -1; float v1 = -1.0f;
        #pragma unroll
        for (int e = 0; e < NE; ++e) if (e != i0 && p[e] > v1) { v1 = p[e]; i1 = e; }
        float invS = 1.0f / (v0 + v1 + 1e-6f);
        sg0[t] = v0 * invS;
        sg1[t] = v1 * invS;
        si0[t] = i0;
        si1[t] = i1;
        s_scale_s[t] = (v0 + v1) * invS;
    }
    __syncthreads();
    if (t == 0) {
        float imp[NE] = {0}, ld[NE] = {0};
        for (int n = 0; n < NB; ++n) {
            imp[si0[n]] += sg0[n];
            imp[si1[n]] += sg1[n];
            ld[si0[n]] += 1.0f;
            ld[si1[n]] += 1.0f;
        }
        d_out[loss_idx] = 0.01f * (cv_sq(imp) + cv_sq(ld));
    }
}

// ---------------------------------------------------------------------------
// K3: basis, pure transform (84us measured).
// ---------------------------------------------------------------------------
__global__ __launch_bounds__(256) void basis_kernel(const float* __restrict__ x,
                                                    const float* __restrict__ bw) {
    const int n = blockIdx.z, h = blockIdx.y, w0 = blockIdx.x * 64;
    const int tid = threadIdx.x;
    const int cisub = tid >> 6;
    const int pix = tid & 63;

    __shared__ __align__(16) float st[64 * 100];
    const float beta2 = 2.25f * bw[1];
    const float beta3 = (300.0f / 9.0f) * bw[2];

    #pragma unroll
    for (int it = 0; it < 8; ++it) {
        const int ci = it * 4 + cisub;
        float v = x[((size_t)(n * CI + ci) * HH + h) * WW + w0 + pix];
        float t = tanhf(v);
        float p2 = t * t - beta2;
        float p3 = t * p2 - beta3 * t;
        st[pix * 100 + ci]      = to_tf32(silu_f(t));
        st[pix * 100 + 32 + ci] = to_tf32(silu_f(p2));
        st[pix * 100 + 64 + ci] = to_tf32(silu_f(p3));
    }
    __syncthreads();

    float4* gout4 = reinterpret_cast<float4*>(
        g_scratch + ((size_t)(n * HH + h) * WW + w0) * GC96);
    const float4* st4 = reinterpret_cast<const float4*>(st);
    #pragma unroll
    for (int it = 0; it < 6; ++it) {
        int f4 = it * 256 + tid;
        int p = f4 / 24, c4 = f4 - p * 24;
        gout4[f4] = st4[p * 25 + c4];
    }
}

// ---------------------------------------------------------------------------
// K4: conv via mma m16n8k8 tf32; A and B fragments both via ldmatrix.
// smem/buffer: gt 5760 floats + wt 2304 floats = 8064 (32.3KB), x2 buffers.
// ---------------------------------------------------------------------------
#define BUFF 8064
#define PLANE 1440
#define IMGS 2880
#define WOFF 5760

__global__ __launch_bounds__(256, 2) void conv_kernel(float* __restrict__ out) {
    extern __shared__ float sm[];
    const int n0 = blockIdx.z * 2;
    const int x0 = blockIdx.x * 16;
    const int y0 = blockIdx.y * 16;
    const int tid = threadIdx.x;
    const int lane = tid & 31;
    const int wid = tid >> 5;
    const int g = lane >> 2;
    const int t = lane & 3;

    uint32_t smbase;
    asm("{ .reg .u64 tt; cvta.to.shared.u64 tt, %1; cvt.u32.u64 %0, tt; }"
        : "=r"(smbase) : "l"(sm));
    const int laneoff = (lane >> 4) * PLANE + (lane & 15) * 4;   // floats

    float acc[2][2][4][4];
    #pragma unroll
    for (int a = 0; a < 2; ++a)
        #pragma unroll
        for (int b = 0; b < 2; ++b)
            #pragma unroll
            for (int c = 0; c < 4; ++c)
                #pragma unroll
                for (int d = 0; d < 4; ++d) acc[a][b][c][d] = 0.0f;

    // ---- prefetch helper (16B granules)
    auto prefetch = [&](int ch, int buf) {
        uint32_t base = smbase + (uint32_t)buf * BUFF * 4u;
        for (int i = tid; i < 1296; i += 256) {
            int img = i / 648;
            int rem = i - img * 648;
            int plane = rem & 1;
            int pos = rem >> 1;
            int r = pos / 18;
            int c = pos - r * 18;
            int gy = y0 - 1 + r, gx = x0 - 1 + c;
            int ok = ((unsigned)gy < 192u) & ((unsigned)gx < 192u);
            int cgy = ok ? gy : 0, cgx = ok ? gx : 0;
            const float* src = &g_scratch[(((size_t)(n0 + img) * HH + cgy) * WW + cgx) * GC96
                                          + ch * 8 + plane * 4];
            uint32_t dst = base + (uint32_t)(img * IMGS + plane * PLANE + r * 80 + c * 4) * 4u;
            cp16(dst, src, ok ? 16 : 0);
        }
        const float* wsrc = w_prep + ch * 2304;
        uint32_t wdst = base + (uint32_t)WOFF * 4u;
        for (int i = tid; i < 576; i += 256)
            cp16(wdst + (uint32_t)i * 16u, wsrc + i * 4, 16);
    };

    prefetch(0, 0);
    CP_COMMIT();

    for (int ch = 0; ch < 12; ++ch) {
        if (ch < 11) {
            prefetch(ch + 1, (ch + 1) & 1);
            CP_COMMIT();
            CP_WAIT(1);
        } else {
            CP_WAIT(0);
        }
        __syncthreads();

        const int bb = ch & 1;
        const uint32_t abase = smbase + (uint32_t)(bb * BUFF + laneoff) * 4u;
        // lane's ldmatrix row address within a weight tap block:
        //   tap block = 256 floats; p block = 128 floats; lane row = lane*4 floats
        const uint32_t wbase = smbase + (uint32_t)(bb * BUFF + WOFF + lane * 4) * 4u;

        #pragma unroll
        for (int kh = 0; kh < 3; ++kh) {
            #pragma unroll
            for (int kw = 0; kw < 3; ++kw) {
                const int tap = kh * 3 + kw;
                unsigned b0[4], b1[4];
                #pragma unroll
                for (int p = 0; p < 2; ++p) {
                    uint32_t waddr = wbase + (uint32_t)(tap * 256 + p * 128) * 4u;
                    asm volatile("ldmatrix.sync.aligned.m8n8.x4.shared.b16 "
                                 "{%0,%1,%2,%3}, [%4];"
                                 : "=r"(b0[2 * p]), "=r"(b1[2 * p]),
                                   "=r"(b0[2 * p + 1]), "=r"(b1[2 * p + 1])
                                 : "r"(waddr));
                }
                #pragma unroll
                for (int img = 0; img < 2; ++img) {
                    #pragma unroll
                    for (int mrow = 0; mrow < 2; ++mrow) {
                        uint32_t addr = abase +
                            (uint32_t)(img * IMGS + (2 * wid + mrow + kh) * 80 + kw * 4) * 4u;
                        unsigned a0, a1, a2, a3;
                        asm volatile("ldmatrix.sync.aligned.m8n8.x4.shared.b16 "
                                     "{%0,%1,%2,%3}, [%4];"
                                     : "=r"(a0), "=r"(a1), "=r"(a2), "=r"(a3)
                                     : "r"(addr));
                        #pragma unroll
                        for (int nc = 0; nc < 4; ++nc)
                            mma_tf32(acc[img][mrow][nc], a0, a1, a2, a3, b0[nc], b1[nc]);
                    }
                }
            }
        }
        __syncthreads();
    }

    // ---- epilogue: + basis0 bias, * gate scale
    #pragma unroll
    for (int img = 0; img < 2; ++img) {
        const float s = s_scale_s[n0 + img];
        #pragma unroll
        for (int mrow = 0; mrow < 2; ++mrow) {
            const int y = y0 + 2 * wid + mrow;
            const int ry = (y == 0) ? 0 : ((y == HH - 1) ? 2 : 1);
            #pragma unroll
            for (int nc = 0; nc < 4; ++nc) {
                #pragma unroll
                for (int e = 0; e < 4; ++e) {
                    const int px = g + ((e >= 2) ? 8 : 0);
                    const int oc = 8 * nc + 2 * t + (e & 1);
                    const int xx = x0 + px;
                    const int cx = (xx == 0) ? 0 : ((xx == WW - 1) ? 2 : 1);
                    out[((size_t)((n0 + img) * CI + oc) * HH + y) * WW + xx] =
                        (acc[img][mrow][nc][e] + bias_g[(ry * 3 + cx) * CI + oc]) * s;
                }
            }
        }
    }
}

// ---------------------------------------------------------------------------
extern "C" void kernel_launch(void* const* d_in, const int* in_sizes, int n_in,
                              void* d_out, int out_size) {
    const float* x  = (const float*)d_in[0];
    const float* wg = (const float*)d_in[1];
    const float* W  = (const float*)d_in[2];
    const float* bw = (const float*)d_in[3];
    float* out = (float*)d_out;
    const int loss_idx = out_size - 1;

    cudaFuncSetAttribute(conv_kernel, cudaFuncAttributeMaxDynamicSharedMemorySize,
                         BUFF * 2 * 4);

    gate_mean_kernel<<<NB * CI, 256>>>(x);       // warms L2 with x for basis
    gating_kernel<<<1, 32>>>(wg, out, loss_idx);
    prep_kernel<<<109, 256>>>(W);
    basis_kernel<<<dim3(3, 192, 16), 256>>>(x, bw);
    conv_kernel<<<dim3(12, 12, 8), 256, BUFF * 2 * 4>>>(out);
}

// round 11
// speedup vs baseline: 3.7242x; 1.0442x over previous
#include <cuda_runtime.h>
#include <cstdint>

// ---------------------------------------------------------------------------
// KAGNMoE round 9:
//  * basis: tanh.approx.f32 + __expf/__fdividef silu (issue-bound -> DRAM floor)
//  * conv: 3-stage cp.async ring, single __syncthreads per chunk
//  (round 8: 328us = conv ~204 + basis ~85 + small ~36; rel_err 1.47e-4)
// ---------------------------------------------------------------------------

#define NB 16
#define CI 32
#define HH 192
#define WW 192
#define HW (HH * WW)
#define GC96 96
#define NE 8

// channel-last basis scratch: [n][h][w][96] (tf32-rounded), ~226 MB
__device__ float g_scratch[(size_t)NB * HH * WW * GC96];
// weights: [ch][tap][p(2)][m(4)][n(8)][k'(4)] tf32, 2304 floats per chunk
__device__ float w_prep[12 * 2304];
__device__ float gate_mean_s[NB * CI];
__device__ float s_scale_s[NB];
__device__ float bias_g[9 * CI];

__device__ __forceinline__ float silu_f(float v) { return v / (1.0f + expf(-v)); }
__device__ __forceinline__ float tanh_fast(float v) {
    float r; asm("tanh.approx.f32 %0, %1;" : "=f"(r) : "f"(v)); return r;
}
__device__ __forceinline__ float silu_fast(float v) {
    return __fdividef(v, 1.0f + __expf(-v));
}
__device__ __forceinline__ float to_tf32(float v) {
    float r; asm("cvt.rna.tf32.f32 %0, %1;" : "=f"(r) : "f"(v)); return r;
}
__device__ __forceinline__ void mma_tf32(float* d, unsigned a0, unsigned a1,
                                         unsigned a2, unsigned a3,
                                         unsigned b0, unsigned b1) {
    asm("mma.sync.aligned.m16n8k8.row.col.f32.tf32.tf32.f32 "
        "{%0,%1,%2,%3}, {%4,%5,%6,%7}, {%8,%9}, {%0,%1,%2,%3};"
        : "+f"(d[0]), "+f"(d[1]), "+f"(d[2]), "+f"(d[3])
        : "r"(a0), "r"(a1), "r"(a2), "r"(a3), "r"(b0), "r"(b1));
}
__device__ __forceinline__ void cp16(uint32_t dst, const void* src, int sz) {
    asm volatile("cp.async.ca.shared.global [%0], [%1], 16, %2;"
                 :: "r"(dst), "l"(src), "r"(sz));
}
#define CP_COMMIT() asm volatile("cp.async.commit_group;")
#define CP_WAIT(n)  asm volatile("cp.async.wait_group %0;" :: "n"(n))

// ---------------------------------------------------------------------------
// K0: weight prep + basis-0 bias (last block). Layout as round 8.
// ---------------------------------------------------------------------------
__global__ void prep_kernel(const float* __restrict__ W) {
    if (blockIdx.x < 108) {
        int j = blockIdx.x * 256 + threadIdx.x;    // < 27648
        int kp = j & 3;
        int n  = (j >> 2) & 7;
        int m  = (j >> 5) & 3;
        int p  = (j >> 7) & 1;
        int tap = (j >> 8) % 9;
        int ch  = (j >> 8) / 9;
        int nc = 2 * p + (m >> 1);
        int cc = (m & 1) * 4 + kp;
        int oc = 8 * nc + n;
        w_prep[j] = to_tf32(W[((size_t)oc * 128 + 32 + ch * 8 + cc) * 9 + tap]);
        return;
    }
    int oc = threadIdx.x;
    if (oc >= 32) return;
    float S[9];
    #pragma unroll
    for (int k = 0; k < 9; ++k) S[k] = 0.0f;
    for (int ci = 0; ci < 32; ++ci)
        #pragma unroll
        for (int k = 0; k < 9; ++k)
            S[k] += W[((size_t)oc * 128 + ci) * 9 + k];
    const float c0 = silu_f(1.0f);
    #pragma unroll
    for (int ry = 0; ry < 3; ++ry)
        #pragma unroll
        for (int cx = 0; cx < 3; ++cx) {
            float b = 0.0f;
            #pragma unroll
            for (int kh = 0; kh < 3; ++kh) {
                if ((ry == 0 && kh == 0) || (ry == 2 && kh == 2)) continue;
                #pragma unroll
                for (int kw = 0; kw < 3; ++kw) {
                    if ((cx == 0 && kw == 0) || (cx == 2 && kw == 2)) continue;
                    b += S[kh * 3 + kw];
                }
            }
            bias_g[(ry * 3 + cx) * CI + oc] = b * c0;
        }
}

// ---------------------------------------------------------------------------
// K1: per-(n,ci) spatial mean of x
// ---------------------------------------------------------------------------
__global__ void gate_mean_kernel(const float* __restrict__ x) {
    const int b = blockIdx.x;
    const float* xp = x + (size_t)b * HW;
    float s = 0.0f;
    for (int i = threadIdx.x; i < HW; i += 256) s += xp[i];
    __shared__ float sh[8];
    #pragma unroll
    for (int o = 16; o > 0; o >>= 1) s += __shfl_down_sync(0xffffffffu, s, o);
    if ((threadIdx.x & 31) == 0) sh[threadIdx.x >> 5] = s;
    __syncthreads();
    if (threadIdx.x < 8) {
        s = sh[threadIdx.x];
        #pragma unroll
        for (int o = 4; o > 0; o >>= 1) s += __shfl_down_sync(0xffu, s, o);
        if (threadIdx.x == 0) gate_mean_s[b] = s * (1.0f / 36864.0f);
    }
}

// ---------------------------------------------------------------------------
// K2: gating
// ---------------------------------------------------------------------------
__device__ float cv_sq(const float* v) {
    float m = 0.0f;
    #pragma unroll
    for (int i = 0; i < NE; ++i) m += v[i];
    m *= (1.0f / NE);
    float var = 0.0f;
    #pragma unroll
    for (int i = 0; i < NE; ++i) { float d = v[i] - m; var += d * d; }
    var *= (1.0f / (NE - 1));
    return var / (m * m + 1e-10f);
}

__global__ void gating_kernel(const float* __restrict__ wg,
                              float* __restrict__ d_out, int loss_idx) {
    __shared__ float sg0[NB], sg1[NB];
    __shared__ int si0[NB], si1[NB];
    int t = threadIdx.x;
    if (t < NB) {
        float l[NE];
        #pragma unroll
        for (int e = 0; e < NE; ++e) {
            float a = 0.0f;
            #pragma unroll
            for (int c = 0; c < CI; ++c) a += gate_mean_s[t * CI + c] * wg[c * NE + e];
            l[e] = a;
        }
        float m = l[0];
        #pragma unroll
        for (int e = 1; e < NE; ++e) m = fmaxf(m, l[e]);
        float p[NE]; float sum = 0.0f;
        #pragma unroll
        for (int e = 0; e < NE; ++e) { p[e] = expf(l[e] - m); sum += p[e]; }
        float inv = 1.0f / sum;
        #pragma unroll
        for (int e = 0; e < NE; ++e) p[e] *= inv;
        int i0 = 0; float v0 = p[0];
        #pragma unroll
        for (int e = 1; e < NE; ++e) if (p[e] > v0) { v0 = p[e]; i0 = e; }
        int i1 = -1; float v1 = -1.0f;
        #pragma unroll
        for (int e = 0; e < NE; ++e) if (e != i0 && p[e] > v1) { v1 = p[e]; i1 = e; }
        float invS = 1.0f / (v0 + v1 + 1e-6f);
        sg0[t] = v0 * invS;
        sg1[t] = v1 * invS;
        si0[t] = i0;
        si1[t] = i1;
        s_scale_s[t] = (v0 + v1) * invS;
    }
    __syncthreads();
    if (t == 0) {
        float imp[NE] = {0}, ld[NE] = {0};
        for (int n = 0; n < NB; ++n) {
            imp[si0[n]] += sg0[n];
            imp[si1[n]] += sg1[n];
            ld[si0[n]] += 1.0f;
            ld[si1[n]] += 1.0f;
        }
        d_out[loss_idx] = 0.01f * (cv_sq(imp) + cv_sq(ld));
    }
}

// ---------------------------------------------------------------------------
// K3: basis, fast-math transform (tanh.approx + __expf).
// ---------------------------------------------------------------------------
__global__ __launch_bounds__(256) void basis_kernel(const float* __restrict__ x,
                                                    const float* __restrict__ bw) {
    const int n = blockIdx.z, h = blockIdx.y, w0 = blockIdx.x * 64;
    const int tid = threadIdx.x;
    const int cisub = tid >> 6;
    const int pix = tid & 63;

    __shared__ __align__(16) float st[64 * 100];
    const float beta2 = 2.25f * bw[1];
    const float beta3 = (300.0f / 9.0f) * bw[2];

    #pragma unroll
    for (int it = 0; it < 8; ++it) {
        const int ci = it * 4 + cisub;
        float v = x[((size_t)(n * CI + ci) * HH + h) * WW + w0 + pix];
        float t = tanh_fast(v);
        float p2 = t * t - beta2;
        float p3 = t * p2 - beta3 * t;
        st[pix * 100 + ci]      = to_tf32(silu_fast(t));
        st[pix * 100 + 32 + ci] = to_tf32(silu_fast(p2));
        st[pix * 100 + 64 + ci] = to_tf32(silu_fast(p3));
    }
    __syncthreads();

    float4* gout4 = reinterpret_cast<float4*>(
        g_scratch + ((size_t)(n * HH + h) * WW + w0) * GC96);
    const float4* st4 = reinterpret_cast<const float4*>(st);
    #pragma unroll
    for (int it = 0; it < 6; ++it) {
        int f4 = it * 256 + tid;
        int p = f4 / 24, c4 = f4 - p * 24;
        gout4[f4] = st4[p * 25 + c4];
    }
}

// ---------------------------------------------------------------------------
// K4: conv via mma m16n8k8 tf32; A/B via ldmatrix; 3-stage cp.async ring,
// one __syncthreads per chunk (wait -> sync -> prefetch(ch+2) -> compute).
// ---------------------------------------------------------------------------
#define BUFF 8064
#define PLANE 1440
#define IMGS 2880
#define WOFF 5760

__global__ __launch_bounds__(256, 2) void conv_kernel(float* __restrict__ out) {
    extern __shared__ float sm[];
    const int n0 = blockIdx.z * 2;
    const int x0 = blockIdx.x * 16;
    const int y0 = blockIdx.y * 16;
    const int tid = threadIdx.x;
    const int lane = tid & 31;
    const int wid = tid >> 5;
    const int g = lane >> 2;
    const int t = lane & 3;

    uint32_t smbase;
    asm("{ .reg .u64 tt; cvta.to.shared.u64 tt, %1; cvt.u32.u64 %0, tt; }"
        : "=r"(smbase) : "l"(sm));
    const int laneoff = (lane >> 4) * PLANE + (lane & 15) * 4;   // floats

    float acc[2][2][4][4];
    #pragma unroll
    for (int a = 0; a < 2; ++a)
        #pragma unroll
        for (int b = 0; b < 2; ++b)
            #pragma unroll
            for (int c = 0; c < 4; ++c)
                #pragma unroll
                for (int d = 0; d < 4; ++d) acc[a][b][c][d] = 0.0f;

    // ---- prefetch helper (16B granules)
    auto prefetch = [&](int ch, int buf) {
        uint32_t base = smbase + (uint32_t)buf * BUFF * 4u;
        for (int i = tid; i < 1296; i += 256) {
            int img = i / 648;
            int rem = i - img * 648;
            int plane = rem & 1;
            int pos = rem >> 1;
            int r = pos / 18;
            int c = pos - r * 18;
            int gy = y0 - 1 + r, gx = x0 - 1 + c;
            int ok = ((unsigned)gy < 192u) & ((unsigned)gx < 192u);
            int cgy = ok ? gy : 0, cgx = ok ? gx : 0;
            const float* src = &g_scratch[(((size_t)(n0 + img) * HH + cgy) * WW + cgx) * GC96
                                          + ch * 8 + plane * 4];
            uint32_t dst = base + (uint32_t)(img * IMGS + plane * PLANE + r * 80 + c * 4) * 4u;
            cp16(dst, src, ok ? 16 : 0);
        }
        const float* wsrc = w_prep + ch * 2304;
        uint32_t wdst = base + (uint32_t)WOFF * 4u;
        for (int i = tid; i < 576; i += 256)
            cp16(wdst + (uint32_t)i * 16u, wsrc + i * 4, 16);
    };

    prefetch(0, 0); CP_COMMIT();
    prefetch(1, 1); CP_COMMIT();

    int buf = 0;
    for (int ch = 0; ch < 12; ++ch) {
        if (ch < 11) { CP_WAIT(1); } else { CP_WAIT(0); }
        __syncthreads();   // chunk data ready; all warps done reading slot (ch+2)%3
        if (ch < 10) {
            prefetch(ch + 2, (ch + 2) % 3);
            CP_COMMIT();
        }

        const uint32_t abase = smbase + (uint32_t)(buf * BUFF + laneoff) * 4u;
        const uint32_t wbase = smbase + (uint32_t)(buf * BUFF + WOFF + lane * 4) * 4u;

        #pragma unroll
        for (int kh = 0; kh < 3; ++kh) {
            #pragma unroll
            for (int kw = 0; kw < 3; ++kw) {
                const int tap = kh * 3 + kw;
                unsigned b0[4], b1[4];
                #pragma unroll
                for (int p = 0; p < 2; ++p) {
                    uint32_t waddr = wbase + (uint32_t)(tap * 256 + p * 128) * 4u;
                    asm volatile("ldmatrix.sync.aligned.m8n8.x4.shared.b16 "
                                 "{%0,%1,%2,%3}, [%4];"
                                 : "=r"(b0[2 * p]), "=r"(b1[2 * p]),
                                   "=r"(b0[2 * p + 1]), "=r"(b1[2 * p + 1])
                                 : "r"(waddr));
                }
                #pragma unroll
                for (int img = 0; img < 2; ++img) {
                    #pragma unroll
                    for (int mrow = 0; mrow < 2; ++mrow) {
                        uint32_t addr = abase +
                            (uint32_t)(img * IMGS + (2 * wid + mrow + kh) * 80 + kw * 4) * 4u;
                        unsigned a0, a1, a2, a3;
                        asm volatile("ldmatrix.sync.aligned.m8n8.x4.shared.b16 "
                                     "{%0,%1,%2,%3}, [%4];"
                                     : "=r"(a0), "=r"(a1), "=r"(a2), "=r"(a3)
                                     : "r"(addr));
                        #pragma unroll
                        for (int nc = 0; nc < 4; ++nc)
                            mma_tf32(acc[img][mrow][nc], a0, a1, a2, a3, b0[nc], b1[nc]);
                    }
                }
            }
        }
        buf = (buf + 1) % 3;
    }

    // ---- epilogue: + basis0 bias, * gate scale
    #pragma unroll
    for (int img = 0; img < 2; ++img) {
        const float s = s_scale_s[n0 + img];
        #pragma unroll
        for (int mrow = 0; mrow < 2; ++mrow) {
            const int y = y0 + 2 * wid + mrow;
            const int ry = (y == 0) ? 0 : ((y == HH - 1) ? 2 : 1);
            #pragma unroll
            for (int nc = 0; nc < 4; ++nc) {
                #pragma unroll
                for (int e = 0; e < 4; ++e) {
                    const int px = g + ((e >= 2) ? 8 : 0);
                    const int oc = 8 * nc + 2 * t + (e & 1);
                    const int xx = x0 + px;
                    const int cx = (xx == 0) ? 0 : ((xx == WW - 1) ? 2 : 1);
                    out[((size_t)((n0 + img) * CI + oc) * HH + y) * WW + xx] =
                        (acc[img][mrow][nc][e] + bias_g[(ry * 3 + cx) * CI + oc]) * s;
                }
            }
        }
    }
}

// ---------------------------------------------------------------------------
extern "C" void kernel_launch(void* const* d_in, const int* in_sizes, int n_in,
                              void* d_out, int out_size) {
    const float* x  = (const float*)d_in[0];
    const float* wg = (const float*)d_in[1];
    const float* W  = (const float*)d_in[2];
    const float* bw = (const float*)d_in[3];
    float* out = (float*)d_out;
    const int loss_idx = out_size - 1;

    cudaFuncSetAttribute(conv_kernel, cudaFuncAttributeMaxDynamicSharedMemorySize,
                         BUFF * 3 * 4);

    gate_mean_kernel<<<NB * CI, 256>>>(x);       // warms L2 with x for basis
    gating_kernel<<<1, 32>>>(wg, out, loss_idx);
    prep_kernel<<<109, 256>>>(W);
    basis_kernel<<<dim3(3, 192, 16), 256>>>(x, bw);
    conv_kernel<<<dim3(12, 12, 8), 256, BUFF * 3 * 4>>>(out);
}

// round 12
// speedup vs baseline: 3.8236x; 1.0267x over previous
#include <cuda_runtime.h>
#include <cstdint>

// ---------------------------------------------------------------------------
// KAGNMoE round 11:
//  * conv: 1 image per CTA (acc 64->32 regs), __launch_bounds__(256,3),
//    3-stage ring @ 20.7KB/buffer -> 3 CTAs/SM (24 warps, +50% latency hiding)
//  * gating folded into prep_kernel (block 109) -- one less launch
//  (round 9: 314us = conv ~220 + basis 55.8 + small ~38)
// ---------------------------------------------------------------------------

#define NB 16
#define CI 32
#define HH 192
#define WW 192
#define HW (HH * WW)
#define GC96 96
#define NE 8

// channel-last basis scratch: [n][h][w][96] (tf32-rounded), ~226 MB
__device__ float g_scratch[(size_t)NB * HH * WW * GC96];
// weights: [ch][tap][p(2)][m(4)][n(8)][k'(4)] tf32, 2304 floats per chunk
__device__ float w_prep[12 * 2304];
__device__ float gate_mean_s[NB * CI];
__device__ float s_scale_s[NB];
__device__ float bias_g[9 * CI];

__device__ __forceinline__ float silu_f(float v) { return v / (1.0f + expf(-v)); }
__device__ __forceinline__ float tanh_fast(float v) {
    float r; asm("tanh.approx.f32 %0, %1;" : "=f"(r) : "f"(v)); return r;
}
__device__ __forceinline__ float silu_fast(float v) {
    return __fdividef(v, 1.0f + __expf(-v));
}
__device__ __forceinline__ float to_tf32(float v) {
    float r; asm("cvt.rna.tf32.f32 %0, %1;" : "=f"(r) : "f"(v)); return r;
}
__device__ __forceinline__ void mma_tf32(float* d, unsigned a0, unsigned a1,
                                         unsigned a2, unsigned a3,
                                         unsigned b0, unsigned b1) {
    asm("mma.sync.aligned.m16n8k8.row.col.f32.tf32.tf32.f32 "
        "{%0,%1,%2,%3}, {%4,%5,%6,%7}, {%8,%9}, {%0,%1,%2,%3};"
        : "+f"(d[0]), "+f"(d[1]), "+f"(d[2]), "+f"(d[3])
        : "r"(a0), "r"(a1), "r"(a2), "r"(a3), "r"(b0), "r"(b1));
}
__device__ __forceinline__ void cp16(uint32_t dst, const void* src, int sz) {
    asm volatile("cp.async.ca.shared.global [%0], [%1], 16, %2;"
                 :: "r"(dst), "l"(src), "r"(sz));
}
#define CP_COMMIT() asm volatile("cp.async.commit_group;")
#define CP_WAIT(n)  asm volatile("cp.async.wait_group %0;" :: "n"(n))

__device__ float cv_sq(const float* v) {
    float m = 0.0f;
    #pragma unroll
    for (int i = 0; i < NE; ++i) m += v[i];
    m *= (1.0f / NE);
    float var = 0.0f;
    #pragma unroll
    for (int i = 0; i < NE; ++i) { float d = v[i] - m; var += d * d; }
    var *= (1.0f / (NE - 1));
    return var / (m * m + 1e-10f);
}

// ---------------------------------------------------------------------------
// K0: per-(n,ci) spatial mean of x  (runs FIRST; also warms L2 with x)
// ---------------------------------------------------------------------------
__global__ void gate_mean_kernel(const float* __restrict__ x) {
    const int b = blockIdx.x;
    const float* xp = x + (size_t)b * HW;
    float s = 0.0f;
    for (int i = threadIdx.x; i < HW; i += 256) s += xp[i];
    __shared__ float sh[8];
    #pragma unroll
    for (int o = 16; o > 0; o >>= 1) s += __shfl_down_sync(0xffffffffu, s, o);
    if ((threadIdx.x & 31) == 0) sh[threadIdx.x >> 5] = s;
    __syncthreads();
    if (threadIdx.x < 8) {
        s = sh[threadIdx.x];
        #pragma unroll
        for (int o = 4; o > 0; o >>= 1) s += __shfl_down_sync(0xffu, s, o);
        if (threadIdx.x == 0) gate_mean_s[b] = s * (1.0f / 36864.0f);
    }
}

// ---------------------------------------------------------------------------
// K1: prep = weights (blocks 0..107) + bias (108) + gating (109).
// gating reads gate_mean_s written by the PREVIOUS launch (stream-ordered).
// ---------------------------------------------------------------------------
__global__ void prep_kernel(const float* __restrict__ W,
                            const float* __restrict__ wg,
                            float* __restrict__ d_out, int loss_idx) {
    if (blockIdx.x < 108) {
        int j = blockIdx.x * 256 + threadIdx.x;    // < 27648
        int kp = j & 3;
        int n  = (j >> 2) & 7;
        int m  = (j >> 5) & 3;
        int p  = (j >> 7) & 1;
        int tap = (j >> 8) % 9;
        int ch  = (j >> 8) / 9;
        int nc = 2 * p + (m >> 1);
        int cc = (m & 1) * 4 + kp;
        int oc = 8 * nc + n;
        w_prep[j] = to_tf32(W[((size_t)oc * 128 + 32 + ch * 8 + cc) * 9 + tap]);
        return;
    }
    if (blockIdx.x == 108) {
        int oc = threadIdx.x;
        if (oc >= 32) return;
        float S[9];
        #pragma unroll
        for (int k = 0; k < 9; ++k) S[k] = 0.0f;
        for (int ci = 0; ci < 32; ++ci)
            #pragma unroll
            for (int k = 0; k < 9; ++k)
                S[k] += W[((size_t)oc * 128 + ci) * 9 + k];
        const float c0 = silu_f(1.0f);
        #pragma unroll
        for (int ry = 0; ry < 3; ++ry)
            #pragma unroll
            for (int cx = 0; cx < 3; ++cx) {
                float b = 0.0f;
                #pragma unroll
                for (int kh = 0; kh < 3; ++kh) {
                    if ((ry == 0 && kh == 0) || (ry == 2 && kh == 2)) continue;
                    #pragma unroll
                    for (int kw = 0; kw < 3; ++kw) {
                        if ((cx == 0 && kw == 0) || (cx == 2 && kw == 2)) continue;
                        b += S[kh * 3 + kw];
                    }
                }
                bias_g[(ry * 3 + cx) * CI + oc] = b * c0;
            }
        return;
    }
    // ---- block 109: gating
    __shared__ float sg0[NB], sg1[NB];
    __shared__ int si0[NB], si1[NB];
    int t = threadIdx.x;
    if (t < NB) {
        float l[NE];
        #pragma unroll
        for (int e = 0; e < NE; ++e) {
            float a = 0.0f;
            #pragma unroll
            for (int c = 0; c < CI; ++c) a += gate_mean_s[t * CI + c] * wg[c * NE + e];
            l[e] = a;
        }
        float m = l[0];
        #pragma unroll
        for (int e = 1; e < NE; ++e) m = fmaxf(m, l[e]);
        float p[NE]; float sum = 0.0f;
        #pragma unroll
        for (int e = 0; e < NE; ++e) { p[e] = expf(l[e] - m); sum += p[e]; }
        float inv = 1.0f / sum;
        #pragma unroll
        for (int e = 0; e < NE; ++e) p[e] *= inv;
        int i0 = 0; float v0 = p[0];
        #pragma unroll
        for (int e = 1; e < NE; ++e) if (p[e] > v0) { v0 = p[e]; i0 = e; }
        int i1 = -1; float v1 = -1.0f;
        #pragma unroll
        for (int e = 0; e < NE; ++e) if (e != i0 && p[e] > v1) { v1 = p[e]; i1 = e; }
        float invS = 1.0f / (v0 + v1 + 1e-6f);
        sg0[t] = v0 * invS;
        sg1[t] = v1 * invS;
        si0[t] = i0;
        si1[t] = i1;
        s_scale_s[t] = (v0 + v1) * invS;
    }
    __syncthreads();
    if (t == 0) {
        float imp[NE] = {0}, ld[NE] = {0};
        for (int n = 0; n < NB; ++n) {
            imp[si0[n]] += sg0[n];
            imp[si1[n]] += sg1[n];
            ld[si0[n]] += 1.0f;
            ld[si1[n]] += 1.0f;
        }
        d_out[loss_idx] = 0.01f * (cv_sq(imp) + cv_sq(ld));
    }
}

// ---------------------------------------------------------------------------
// K2: basis, fast-math transform (55.8us measured).
// ---------------------------------------------------------------------------
__global__ __launch_bounds__(256) void basis_kernel(const float* __restrict__ x,
                                                    const float* __restrict__ bw) {
    const int n = blockIdx.z, h = blockIdx.y, w0 = blockIdx.x * 64;
    const int tid = threadIdx.x;
    const int cisub = tid >> 6;
    const int pix = tid & 63;

    __shared__ __align__(16) float st[64 * 100];
    const float beta2 = 2.25f * bw[1];
    const float beta3 = (300.0f / 9.0f) * bw[2];

    #pragma unroll
    for (int it = 0; it < 8; ++it) {
        const int ci = it * 4 + cisub;
        float v = x[((size_t)(n * CI + ci) * HH + h) * WW + w0 + pix];
        float t = tanh_fast(v);
        float p2 = t * t - beta2;
        float p3 = t * p2 - beta3 * t;
        st[pix * 100 + ci]      = to_tf32(silu_fast(t));
        st[pix * 100 + 32 + ci] = to_tf32(silu_fast(p2));
        st[pix * 100 + 64 + ci] = to_tf32(silu_fast(p3));
    }
    __syncthreads();

    float4* gout4 = reinterpret_cast<float4*>(
        g_scratch + ((size_t)(n * HH + h) * WW + w0) * GC96);
    const float4* st4 = reinterpret_cast<const float4*>(st);
    #pragma unroll
    for (int it = 0; it < 6; ++it) {
        int f4 = it * 256 + tid;
        int p = f4 / 24, c4 = f4 - p * 24;
        gout4[f4] = st4[p * 25 + c4];
    }
}

// ---------------------------------------------------------------------------
// K3: conv, 1 image per CTA. mma m16n8k8 tf32, A/B via ldmatrix,
// 3-stage cp.async ring. smem/buffer = 2880 (g) + 2304 (w) = 5184 floats.
// ---------------------------------------------------------------------------
#define BUFF 5184
#define PLANE 1440
#define WOFF 2880

__global__ __launch_bounds__(256, 3) void conv_kernel(float* __restrict__ out) {
    extern __shared__ float sm[];
    const int n = blockIdx.z;
    const int x0 = blockIdx.x * 16;
    const int y0 = blockIdx.y * 16;
    const int tid = threadIdx.x;
    const int lane = tid & 31;
    const int wid = tid >> 5;
    const int g = lane >> 2;
    const int t = lane & 3;

    uint32_t smbase;
    asm("{ .reg .u64 tt; cvta.to.shared.u64 tt, %1; cvt.u32.u64 %0, tt; }"
        : "=r"(smbase) : "l"(sm));
    const int laneoff = (lane >> 4) * PLANE + (lane & 15) * 4;   // floats

    float acc[2][4][4];
    #pragma unroll
    for (int b = 0; b < 2; ++b)
        #pragma unroll
        for (int c = 0; c < 4; ++c)
            #pragma unroll
            for (int d = 0; d < 4; ++d) acc[b][c][d] = 0.0f;

    // ---- prefetch helper (16B granules): 648 g + 576 w = 1224 cp16
    auto prefetch = [&](int ch, int buf) {
        uint32_t base = smbase + (uint32_t)buf * BUFF * 4u;
        for (int i = tid; i < 648; i += 256) {
            int plane = i & 1;
            int pos = i >> 1;
            int r = pos / 18;
            int c = pos - r * 18;
            int gy = y0 - 1 + r, gx = x0 - 1 + c;
            int ok = ((unsigned)gy < 192u) & ((unsigned)gx < 192u);
            int cgy = ok ? gy : 0, cgx = ok ? gx : 0;
            const float* src = &g_scratch[(((size_t)n * HH + cgy) * WW + cgx) * GC96
                                          + ch * 8 + plane * 4];
            uint32_t dst = base + (uint32_t)(plane * PLANE + r * 80 + c * 4) * 4u;
            cp16(dst, src, ok ? 16 : 0);
        }
        const float* wsrc = w_prep + ch * 2304;
        uint32_t wdst = base + (uint32_t)WOFF * 4u;
        for (int i = tid; i < 576; i += 256)
            cp16(wdst + (uint32_t)i * 16u, wsrc + i * 4, 16);
    };

    prefetch(0, 0); CP_COMMIT();
    prefetch(1, 1); CP_COMMIT();

    int buf = 0;
    for (int ch = 0; ch < 12; ++ch) {
        if (ch < 11) { CP_WAIT(1); } else { CP_WAIT(0); }
        __syncthreads();
        if (ch < 10) {
            prefetch(ch + 2, (ch + 2) % 3);
            CP_COMMIT();
        }

        const uint32_t abase = smbase + (uint32_t)(buf * BUFF + laneoff) * 4u;
        const uint32_t wbase = smbase + (uint32_t)(buf * BUFF + WOFF + lane * 4) * 4u;

        #pragma unroll
        for (int kh = 0; kh < 3; ++kh) {
            #pragma unroll
            for (int kw = 0; kw < 3; ++kw) {
                const int tap = kh * 3 + kw;
                unsigned b0[4], b1[4];
                #pragma unroll
                for (int p = 0; p < 2; ++p) {
                    uint32_t waddr = wbase + (uint32_t)(tap * 256 + p * 128) * 4u;
                    asm volatile("ldmatrix.sync.aligned.m8n8.x4.shared.b16 "
                                 "{%0,%1,%2,%3}, [%4];"
                                 : "=r"(b0[2 * p]), "=r"(b1[2 * p]),
                                   "=r"(b0[2 * p + 1]), "=r"(b1[2 * p + 1])
                                 : "r"(waddr));
                }
                #pragma unroll
                for (int mrow = 0; mrow < 2; ++mrow) {
                    uint32_t addr = abase +
                        (uint32_t)((2 * wid + mrow + kh) * 80 + kw * 4) * 4u;
                    unsigned a0, a1, a2, a3;
                    asm volatile("ldmatrix.sync.aligned.m8n8.x4.shared.b16 "
                                 "{%0,%1,%2,%3}, [%4];"
                                 : "=r"(a0), "=r"(a1), "=r"(a2), "=r"(a3)
                                 : "r"(addr));
                    #pragma unroll
                    for (int nc = 0; nc < 4; ++nc)
                        mma_tf32(acc[mrow][nc], a0, a1, a2, a3, b0[nc], b1[nc]);
                }
            }
        }
        buf = (buf + 1) % 3;
    }

    // ---- epilogue: + basis0 bias, * gate scale
    const float s = s_scale_s[n];
    #pragma unroll
    for (int mrow = 0; mrow < 2; ++mrow) {
        const int y = y0 + 2 * wid + mrow;
        const int ry = (y == 0) ? 0 : ((y == HH - 1) ? 2 : 1);
        #pragma unroll
        for (int nc = 0; nc < 4; ++nc) {
            #pragma unroll
            for (int e = 0; e < 4; ++e) {
                const int px = g + ((e >= 2) ? 8 : 0);
                const int oc = 8 * nc + 2 * t + (e & 1);
                const int xx = x0 + px;
                const int cx = (xx == 0) ? 0 : ((xx == WW - 1) ? 2 : 1);
                out[((size_t)(n * CI + oc) * HH + y) * WW + xx] =
                    (acc[mrow][nc][e] + bias_g[(ry * 3 + cx) * CI + oc]) * s;
            }
        }
    }
}

// ---------------------------------------------------------------------------
extern "C" void kernel_launch(void* const* d_in, const int* in_sizes, int n_in,
                              void* d_out, int out_size) {
    const float* x  = (const float*)d_in[0];
    const float* wg = (const float*)d_in[1];
    const float* W  = (const float*)d_in[2];
    const float* bw = (const float*)d_in[3];
    float* out = (float*)d_out;
    const int loss_idx = out_size - 1;

    cudaFuncSetAttribute(conv_kernel, cudaFuncAttributeMaxDynamicSharedMemorySize,
                         BUFF * 3 * 4);

    gate_mean_kernel<<<NB * CI, 256>>>(x);
    prep_kernel<<<110, 256>>>(W, wg, out, loss_idx);   // weights+bias+gating
    basis_kernel<<<dim3(3, 192, 16), 256>>>(x, bw);
    conv_kernel<<<dim3(12, 12, 16), 256, BUFF * 3 * 4>>>(out);
}

// round 13
// speedup vs baseline: 5.9481x; 1.5556x over previous
#include <cuda_runtime.h>
#include <cuda_fp16.h>
#include <cstdint>

// ---------------------------------------------------------------------------
// KAGNMoE round 12: fp16 conv operands (same 2^-11 mantissa as tf32).
//   mma m16n8k16.f16 / f32-accum: 16-channel chunks (6 instead of 12) ->
//   LDSM wavefronts, smem bytes, tensor instrs all halve. g_scratch half.
//   A-tile 48B/pixel stride: ldmatrix banks {0,12,24,4,16,28,8,20} perfect.
// (round 11: 306us = conv 218.4 (L1 81.5%) + basis 55.8 + small ~32)
// ---------------------------------------------------------------------------

#define NB 16
#define CI 32
#define HH 192
#define WW 192
#define HW (HH * WW)
#define GC96 96
#define NE 8

// channel-last basis scratch: [n][h][w][96] fp16, ~113 MB
__device__ __half g_scratch[(size_t)NB * HH * WW * GC96];
// weights fp16: [ch6][tap9][ng4][kk2][row8][col8] halves (27648 total)
__device__ __half w_prep[6 * 4608];
__device__ float gate_mean_s[NB * CI];
__device__ float s_scale_s[NB];
__device__ float bias_g[9 * CI];

__device__ __forceinline__ float silu_f(float v) { return v / (1.0f + expf(-v)); }
__device__ __forceinline__ float tanh_fast(float v) {
    float r; asm("tanh.approx.f32 %0, %1;" : "=f"(r) : "f"(v)); return r;
}
__device__ __forceinline__ float silu_fast(float v) {
    return __fdividef(v, 1.0f + __expf(-v));
}
__device__ __forceinline__ void mma_f16(float* d, unsigned a0, unsigned a1,
                                        unsigned a2, unsigned a3,
                                        unsigned b0, unsigned b1) {
    asm("mma.sync.aligned.m16n8k16.row.col.f32.f16.f16.f32 "
        "{%0,%1,%2,%3}, {%4,%5,%6,%7}, {%8,%9}, {%0,%1,%2,%3};"
        : "+f"(d[0]), "+f"(d[1]), "+f"(d[2]), "+f"(d[3])
        : "r"(a0), "r"(a1), "r"(a2), "r"(a3), "r"(b0), "r"(b1));
}
__device__ __forceinline__ void cp16(uint32_t dst, const void* src, int sz) {
    asm volatile("cp.async.ca.shared.global [%0], [%1], 16, %2;"
                 :: "r"(dst), "l"(src), "r"(sz));
}
#define CP_COMMIT() asm volatile("cp.async.commit_group;")
#define CP_WAIT(n)  asm volatile("cp.async.wait_group %0;" :: "n"(n))

__device__ float cv_sq(const float* v) {
    float m = 0.0f;
    #pragma unroll
    for (int i = 0; i < NE; ++i) m += v[i];
    m *= (1.0f / NE);
    float var = 0.0f;
    #pragma unroll
    for (int i = 0; i < NE; ++i) { float d = v[i] - m; var += d * d; }
    var *= (1.0f / (NE - 1));
    return var / (m * m + 1e-10f);
}

// ---------------------------------------------------------------------------
// K0: per-(n,ci) spatial mean of x (runs first; warms L2 with x)
// ---------------------------------------------------------------------------
__global__ void gate_mean_kernel(const float* __restrict__ x) {
    const int b = blockIdx.x;
    const float* xp = x + (size_t)b * HW;
    float s = 0.0f;
    for (int i = threadIdx.x; i < HW; i += 256) s += xp[i];
    __shared__ float sh[8];
    #pragma unroll
    for (int o = 16; o > 0; o >>= 1) s += __shfl_down_sync(0xffffffffu, s, o);
    if ((threadIdx.x & 31) == 0) sh[threadIdx.x >> 5] = s;
    __syncthreads();
    if (threadIdx.x < 8) {
        s = sh[threadIdx.x];
        #pragma unroll
        for (int o = 4; o > 0; o >>= 1) s += __shfl_down_sync(0xffu, s, o);
        if (threadIdx.x == 0) gate_mean_s[b] = s * (1.0f / 36864.0f);
    }
}

// ---------------------------------------------------------------------------
// K1: prep = fp16 weights (blocks 0..107) + bias (108) + gating (109).
// Weight layout per chunk: [tap][ng][kk][row n(8)][col k(8)] halves, so a
// single ldmatrix.x4 at (tap, ngpair p) yields {b0[2p],b1[2p],b0[2p+1],b1[2p+1]}.
// ---------------------------------------------------------------------------
__global__ void prep_kernel(const float* __restrict__ W,
                            const float* __restrict__ wg,
                            float* __restrict__ d_out, int loss_idx) {
    if (blockIdx.x < 108) {
        int j = blockIdx.x * 256 + threadIdx.x;    // < 27648 halves
        int ch = j / 4608;
        int jj = j - ch * 4608;
        int tap = jj / 512;
        int r0 = jj - tap * 512;
        int ng = r0 >> 7;
        int r1 = r0 & 127;
        int kk = r1 >> 6;
        int r2 = r1 & 63;
        int row = r2 >> 3;      // n within group
        int col = r2 & 7;       // k within half
        int oc = ng * 8 + row;
        int cc = kk * 8 + col;  // channel within 16-ch chunk
        w_prep[j] = __float2half_rn(
            W[((size_t)oc * 128 + 32 + ch * 16 + cc) * 9 + tap]);
        return;
    }
    if (blockIdx.x == 108) {
        int oc = threadIdx.x;
        if (oc >= 32) return;
        float S[9];
        #pragma unroll
        for (int k = 0; k < 9; ++k) S[k] = 0.0f;
        for (int ci = 0; ci < 32; ++ci)
            #pragma unroll
            for (int k = 0; k < 9; ++k)
                S[k] += W[((size_t)oc * 128 + ci) * 9 + k];
        const float c0 = silu_f(1.0f);
        #pragma unroll
        for (int ry = 0; ry < 3; ++ry)
            #pragma unroll
            for (int cx = 0; cx < 3; ++cx) {
                float b = 0.0f;
                #pragma unroll
                for (int kh = 0; kh < 3; ++kh) {
                    if ((ry == 0 && kh == 0) || (ry == 2 && kh == 2)) continue;
                    #pragma unroll
                    for (int kw = 0; kw < 3; ++kw) {
                        if ((cx == 0 && kw == 0) || (cx == 2 && kw == 2)) continue;
                        b += S[kh * 3 + kw];
                    }
                }
                bias_g[(ry * 3 + cx) * CI + oc] = b * c0;
            }
        return;
    }
    // ---- block 109: gating (reads gate_mean_s from previous launch)
    __shared__ float sg0[NB], sg1[NB];
    __shared__ int si0[NB], si1[NB];
    int t = threadIdx.x;
    if (t < NB) {
        float l[NE];
        #pragma unroll
        for (int e = 0; e < NE; ++e) {
            float a = 0.0f;
            #pragma unroll
            for (int c = 0; c < CI; ++c) a += gate_mean_s[t * CI + c] * wg[c * NE + e];
            l[e] = a;
        }
        float m = l[0];
        #pragma unroll
        for (int e = 1; e < NE; ++e) m = fmaxf(m, l[e]);
        float p[NE]; float sum = 0.0f;
        #pragma unroll
        for (int e = 0; e < NE; ++e) { p[e] = expf(l[e] - m); sum += p[e]; }
        float inv = 1.0f / sum;
        #pragma unroll
        for (int e = 0; e < NE; ++e) p[e] *= inv;
        int i0 = 0; float v0 = p[0];
        #pragma unroll
        for (int e = 1; e < NE; ++e) if (p[e] > v0) { v0 = p[e]; i0 = e; }
        int i1 = -1; float v1 = -1.0f;
        #pragma unroll
        for (int e = 0; e < NE; ++e) if (e != i0 && p[e] > v1) { v1 = p[e]; i1 = e; }
        float invS = 1.0f / (v0 + v1 + 1e-6f);
        sg0[t] = v0 * invS;
        sg1[t] = v1 * invS;
        si0[t] = i0;
        si1[t] = i1;
        s_scale_s[t] = (v0 + v1) * invS;
    }
    __syncthreads();
    if (t == 0) {
        float imp[NE] = {0}, ld[NE] = {0};
        for (int n = 0; n < NB; ++n) {
            imp[si0[n]] += sg0[n];
            imp[si1[n]] += sg1[n];
            ld[si0[n]] += 1.0f;
            ld[si1[n]] += 1.0f;
        }
        d_out[loss_idx] = 0.01f * (cv_sq(imp) + cv_sq(ld));
    }
}

// ---------------------------------------------------------------------------
// K2: basis, fast-math, fp16 output. smem st: half[64 px][104] (208B rows).
// ---------------------------------------------------------------------------
__global__ __launch_bounds__(256) void basis_kernel(const float* __restrict__ x,
                                                    const float* __restrict__ bw) {
    const int n = blockIdx.z, h = blockIdx.y, w0 = blockIdx.x * 64;
    const int tid = threadIdx.x;
    const int cisub = tid >> 6;
    const int pix = tid & 63;

    __shared__ __align__(16) __half st[64 * 104];
    const float beta2 = 2.25f * bw[1];
    const float beta3 = (300.0f / 9.0f) * bw[2];

    #pragma unroll
    for (int it = 0; it < 8; ++it) {
        const int ci = it * 4 + cisub;
        float v = x[((size_t)(n * CI + ci) * HH + h) * WW + w0 + pix];
        float t = tanh_fast(v);
        float p2 = t * t - beta2;
        float p3 = t * p2 - beta3 * t;
        st[pix * 104 + ci]      = __float2half_rn(silu_fast(t));
        st[pix * 104 + 32 + ci] = __float2half_rn(silu_fast(p2));
        st[pix * 104 + 64 + ci] = __float2half_rn(silu_fast(p3));
    }
    __syncthreads();

    // coalesced drain: 64 px * 12 uint4 (96 halves) = 768 uint4
    uint4* gout4 = reinterpret_cast<uint4*>(
        g_scratch + ((size_t)(n * HH + h) * WW + w0) * GC96);
    const uint4* st4 = reinterpret_cast<const uint4*>(st);
    #pragma unroll
    for (int it = 0; it < 3; ++it) {
        int f4 = it * 256 + tid;
        int p = f4 / 12, c4 = f4 - p * 12;
        gout4[f4] = st4[p * 13 + c4];
    }
}

// ---------------------------------------------------------------------------
// K3: conv, fp16 mma m16n8k16, 16-channel chunks (6 total), A/B via ldmatrix,
// 3-stage cp.async ring. Buffer: g 18*18*48B = 15552B + w 9216B = 24768B.
// A tile: [r18][c18][48B] (32B data + 16B pad -> conflict-free ldmatrix).
// ---------------------------------------------------------------------------
#define BUFFB 24768
#define WOFFB 15552

__global__ __launch_bounds__(256, 3) void conv_kernel(float* __restrict__ out) {
    extern __shared__ char smc[];
    const int n = blockIdx.z;
    const int x0 = blockIdx.x * 16;
    const int y0 = blockIdx.y * 16;
    const int tid = threadIdx.x;
    const int lane = tid & 31;
    const int wid = tid >> 5;
    const int g = lane >> 2;
    const int t = lane & 3;

    uint32_t smbase;
    asm("{ .reg .u64 tt; cvta.to.shared.u64 tt, %1; cvt.u32.u64 %0, tt; }"
        : "=r"(smbase) : "l"(smc));
    // A-frag lane offset: rows m=(lane&15) at 48B stride, k-half from bit4
    const uint32_t alane = (uint32_t)(lane & 15) * 48u + (uint32_t)(lane >> 4) * 16u;

    float acc[2][4][4];
    #pragma unroll
    for (int b = 0; b < 2; ++b)
        #pragma unroll
        for (int c = 0; c < 4; ++c)
            #pragma unroll
            for (int d = 0; d < 4; ++d) acc[b][c][d] = 0.0f;

    // ---- prefetch: 648 g-cp16 (2 per pixel) + 576 w-cp16
    auto prefetch = [&](int ch, int buf) {
        uint32_t base = smbase + (uint32_t)buf * BUFFB;
        for (int i = tid; i < 648; i += 256) {
            int plane = i & 1;            // which 8-channel 16B half
            int pos = i >> 1;
            int r = pos / 18;
            int c = pos - r * 18;
            int gy = y0 - 1 + r, gx = x0 - 1 + c;
            int ok = ((unsigned)gy < 192u) & ((unsigned)gx < 192u);
            int cgy = ok ? gy : 0, cgx = ok ? gx : 0;
            const __half* src = g_scratch + (((size_t)n * HH + cgy) * WW + cgx) * GC96
                                + ch * 16 + plane * 8;
            uint32_t dst = base + (uint32_t)(r * 864 + c * 48 + plane * 16);
            cp16(dst, src, ok ? 16 : 0);
        }
        const __half* wsrc = w_prep + ch * 4608;
        uint32_t wdst = base + WOFFB;
        for (int i = tid; i < 576; i += 256)
            cp16(wdst + (uint32_t)i * 16u, wsrc + i * 8, 16);
    };

    prefetch(0, 0); CP_COMMIT();
    prefetch(1, 1); CP_COMMIT();

    int buf = 0;
    for (int ch = 0; ch < 6; ++ch) {
        if (ch < 5) { CP_WAIT(1); } else { CP_WAIT(0); }
        __syncthreads();
        if (ch < 4) {
            prefetch(ch + 2, (ch + 2) % 3);
            CP_COMMIT();
        }

        const uint32_t abase = smbase + (uint32_t)buf * BUFFB + alane;
        const uint32_t wbase = smbase + (uint32_t)buf * BUFFB + WOFFB
                               + (uint32_t)lane * 16u;

        #pragma unroll
        for (int kh = 0; kh < 3; ++kh) {
            #pragma unroll
            for (int kw = 0; kw < 3; ++kw) {
                const int tap = kh * 3 + kw;
                unsigned b0[4], b1[4];
                #pragma unroll
                for (int p = 0; p < 2; ++p) {
                    uint32_t waddr = wbase + (uint32_t)(tap * 1024 + p * 512);
                    asm volatile("ldmatrix.sync.aligned.m8n8.x4.shared.b16 "
                                 "{%0,%1,%2,%3}, [%4];"
                                 : "=r"(b0[2 * p]), "=r"(b1[2 * p]),
                                   "=r"(b0[2 * p + 1]), "=r"(b1[2 * p + 1])
                                 : "r"(waddr));
                }
                #pragma unroll
                for (int mrow = 0; mrow < 2; ++mrow) {
                    uint32_t addr = abase +
                        (uint32_t)((2 * wid + mrow + kh) * 864 + kw * 48);
                    unsigned a0, a1, a2, a3;
                    asm volatile("ldmatrix.sync.aligned.m8n8.x4.shared.b16 "
                                 "{%0,%1,%2,%3}, [%4];"
                                 : "=r"(a0), "=r"(a1), "=r"(a2), "=r"(a3)
                                 : "r"(addr));
                    #pragma unroll
                    for (int nc = 0; nc < 4; ++nc)
                        mma_f16(acc[mrow][nc], a0, a1, a2, a3, b0[nc], b1[nc]);
                }
            }
        }
        buf = (buf + 1) % 3;
    }

    // ---- epilogue: + basis0 bias, * gate scale
    const float s = s_scale_s[n];
    #pragma unroll
    for (int mrow = 0; mrow < 2; ++mrow) {
        const int y = y0 + 2 * wid + mrow;
        const int ry = (y == 0) ? 0 : ((y == HH - 1) ? 2 : 1);
        #pragma unroll
        for (int nc = 0; nc < 4; ++nc) {
            #pragma unroll
            for (int e = 0; e < 4; ++e) {
                const int px = g + ((e >= 2) ? 8 : 0);
                const int oc = 8 * nc + 2 * t + (e & 1);
                const int xx = x0 + px;
                const int cx = (xx == 0) ? 0 : ((xx == WW - 1) ? 2 : 1);
                out[((size_t)(n * CI + oc) * HH + y) * WW + xx] =
                    (acc[mrow][nc][e] + bias_g[(ry * 3 + cx) * CI + oc]) * s;
            }
        }
    }
}

// ---------------------------------------------------------------------------
extern "C" void kernel_launch(void* const* d_in, const int* in_sizes, int n_in,
                              void* d_out, int out_size) {
    const float* x  = (const float*)d_in[0];
    const float* wg = (const float*)d_in[1];
    const float* W  = (const float*)d_in[2];
    const float* bw = (const float*)d_in[3];
    float* out = (float*)d_out;
    const int loss_idx = out_size - 1;

    cudaFuncSetAttribute(conv_kernel, cudaFuncAttributeMaxDynamicSharedMemorySize,
                         BUFFB * 3);

    gate_mean_kernel<<<NB * CI, 256>>>(x);
    prep_kernel<<<110, 256>>>(W, wg, out, loss_idx);
    basis_kernel<<<dim3(3, 192, 16), 256>>>(x, bw);
    conv_kernel<<<dim3(12, 12, 16), 256, BUFFB * 3>>>(out);
}

// round 15
// speedup vs baseline: 6.7899x; 1.1415x over previous
#include <cuda_runtime.h>
#include <cuda_fp16.h>
#include <cstdint>

// ---------------------------------------------------------------------------
// KAGNMoE round 14: R13 minus the regression.
//   gate_mean reverted to scalar strided loads (summation ORDER matters:
//   float4 reorder flipped a borderline top-2 index -> load-count cv^2 off
//   by 28%). Conv keeps the R13 16x32 / 4-rows-per-warp A-reuse design
//   (128B/MMA) -- unvalidated by timing, not implicated in the failure.
// ---------------------------------------------------------------------------

#define NB 16
#define CI 32
#define HH 192
#define WW 192
#define HW (HH * WW)
#define GC96 96
#define NE 8

// channel-last basis scratch: [n][h][w][96] fp16, ~113 MB
__device__ __half g_scratch[(size_t)NB * HH * WW * GC96];
// weights fp16: [ch6][tap9][ng4][kk2][row8][col8] halves (27648 total)
__device__ __half w_prep[6 * 4608];
__device__ float gate_mean_s[NB * CI];
__device__ float s_scale_s[NB];
__device__ float bias_g[9 * CI];

__device__ __forceinline__ float silu_f(float v) { return v / (1.0f + expf(-v)); }
__device__ __forceinline__ float tanh_fast(float v) {
    float r; asm("tanh.approx.f32 %0, %1;" : "=f"(r) : "f"(v)); return r;
}
__device__ __forceinline__ float silu_fast(float v) {
    return __fdividef(v, 1.0f + __expf(-v));
}
__device__ __forceinline__ void mma_f16(float* d, unsigned a0, unsigned a1,
                                        unsigned a2, unsigned a3,
                                        unsigned b0, unsigned b1) {
    asm("mma.sync.aligned.m16n8k16.row.col.f32.f16.f16.f32 "
        "{%0,%1,%2,%3}, {%4,%5,%6,%7}, {%8,%9}, {%0,%1,%2,%3};"
        : "+f"(d[0]), "+f"(d[1]), "+f"(d[2]), "+f"(d[3])
        : "r"(a0), "r"(a1), "r"(a2), "r"(a3), "r"(b0), "r"(b1));
}
__device__ __forceinline__ void cp16(uint32_t dst, const void* src, int sz) {
    asm volatile("cp.async.ca.shared.global [%0], [%1], 16, %2;"
                 :: "r"(dst), "l"(src), "r"(sz));
}
#define CP_COMMIT() asm volatile("cp.async.commit_group;")
#define CP_WAIT(n)  asm volatile("cp.async.wait_group %0;" :: "n"(n))

__device__ float cv_sq(const float* v) {
    float m = 0.0f;
    #pragma unroll
    for (int i = 0; i < NE; ++i) m += v[i];
    m *= (1.0f / NE);
    float var = 0.0f;
    #pragma unroll
    for (int i = 0; i < NE; ++i) { float d = v[i] - m; var += d * d; }
    var *= (1.0f / (NE - 1));
    return var / (m * m + 1e-10f);
}

// ---------------------------------------------------------------------------
// K0: per-(n,ci) spatial mean of x.
// EXACT R12 structure (scalar, stride-256): summation order is part of the
// correctness contract for the loss's top-2 index selection. Do not reorder.
// ---------------------------------------------------------------------------
__global__ void gate_mean_kernel(const float* __restrict__ x) {
    const int b = blockIdx.x;
    const float* xp = x + (size_t)b * HW;
    float s = 0.0f;
    for (int i = threadIdx.x; i < HW; i += 256) s += xp[i];
    __shared__ float sh[8];
    #pragma unroll
    for (int o = 16; o > 0; o >>= 1) s += __shfl_down_sync(0xffffffffu, s, o);
    if ((threadIdx.x & 31) == 0) sh[threadIdx.x >> 5] = s;
    __syncthreads();
    if (threadIdx.x < 8) {
        s = sh[threadIdx.x];
        #pragma unroll
        for (int o = 4; o > 0; o >>= 1) s += __shfl_down_sync(0xffu, s, o);
        if (threadIdx.x == 0) gate_mean_s[b] = s * (1.0f / 36864.0f);
    }
}

// ---------------------------------------------------------------------------
// K1: prep = fp16 weights (blocks 0..107) + bias (108) + gating (109).
// ---------------------------------------------------------------------------
__global__ void prep_kernel(const float* __restrict__ W,
                            const float* __restrict__ wg,
                            float* __restrict__ d_out, int loss_idx) {
    if (blockIdx.x < 108) {
        int j = blockIdx.x * 256 + threadIdx.x;    // < 27648 halves
        int ch = j / 4608;
        int jj = j - ch * 4608;
        int tap = jj / 512;
        int r0 = jj - tap * 512;
        int ng = r0 >> 7;
        int r1 = r0 & 127;
        int kk = r1 >> 6;
        int r2 = r1 & 63;
        int row = r2 >> 3;
        int col = r2 & 7;
        int oc = ng * 8 + row;
        int cc = kk * 8 + col;
        w_prep[j] = __float2half_rn(
            W[((size_t)oc * 128 + 32 + ch * 16 + cc) * 9 + tap]);
        return;
    }
    if (blockIdx.x == 108) {
        int oc = threadIdx.x;
        if (oc >= 32) return;
        float S[9];
        #pragma unroll
        for (int k = 0; k < 9; ++k) S[k] = 0.0f;
        for (int ci = 0; ci < 32; ++ci)
            #pragma unroll
            for (int k = 0; k < 9; ++k)
                S[k] += W[((size_t)oc * 128 + ci) * 9 + k];
        const float c0 = silu_f(1.0f);
        #pragma unroll
        for (int ry = 0; ry < 3; ++ry)
            #pragma unroll
            for (int cx = 0; cx < 3; ++cx) {
                float b = 0.0f;
                #pragma unroll
                for (int kh = 0; kh < 3; ++kh) {
                    if ((ry == 0 && kh == 0) || (ry == 2 && kh == 2)) continue;
                    #pragma unroll
                    for (int kw = 0; kw < 3; ++kw) {
                        if ((cx == 0 && kw == 0) || (cx == 2 && kw == 2)) continue;
                        b += S[kh * 3 + kw];
                    }
                }
                bias_g[(ry * 3 + cx) * CI + oc] = b * c0;
            }
        return;
    }
    // ---- block 109: gating
    __shared__ float sg0[NB], sg1[NB];
    __shared__ int si0[NB], si1[NB];
    int t = threadIdx.x;
    if (t < NB) {
        float l[NE];
        #pragma unroll
        for (int e = 0; e < NE; ++e) {
            float a = 0.0f;
            #pragma unroll
            for (int c = 0; c < CI; ++c) a += gate_mean_s[t * CI + c] * wg[c * NE + e];
            l[e] = a;
        }
        float m = l[0];
        #pragma unroll
        for (int e = 1; e < NE; ++e) m = fmaxf(m, l[e]);
        float p[NE]; float sum = 0.0f;
        #pragma unroll
        for (int e = 0; e < NE; ++e) { p[e] = expf(l[e] - m); sum += p[e]; }
        float inv = 1.0f / sum;
        #pragma unroll
        for (int e = 0; e < NE; ++e) p[e] *= inv;
        int i0 = 0; float v0 = p[0];
        #pragma unroll
        for (int e = 1; e < NE; ++e) if (p[e] > v0) { v0 = p[e]; i0 = e; }
        int i1 = -1; float v1 = -1.0f;
        #pragma unroll
        for (int e = 0; e < NE; ++e) if (e != i0 && p[e] > v1) { v1 = p[e]; i1 = e; }
        float invS = 1.0f / (v0 + v1 + 1e-6f);
        sg0[t] = v0 * invS;
        sg1[t] = v1 * invS;
        si0[t] = i0;
        si1[t] = i1;
        s_scale_s[t] = (v0 + v1) * invS;
    }
    __syncthreads();
    if (t == 0) {
        float imp[NE] = {0}, ld[NE] = {0};
        for (int n = 0; n < NB; ++n) {
            imp[si0[n]] += sg0[n];
            imp[si1[n]] += sg1[n];
            ld[si0[n]] += 1.0f;
            ld[si1[n]] += 1.0f;
        }
        d_out[loss_idx] = 0.01f * (cv_sq(imp) + cv_sq(ld));
    }
}

// ---------------------------------------------------------------------------
// K2: basis, fast-math, fp16 output (unchanged; ~42us).
// ---------------------------------------------------------------------------
__global__ __launch_bounds__(256) void basis_kernel(const float* __restrict__ x,
                                                    const float* __restrict__ bw) {
    const int n = blockIdx.z, h = blockIdx.y, w0 = blockIdx.x * 64;
    const int tid = threadIdx.x;
    const int cisub = tid >> 6;
    const int pix = tid & 63;

    __shared__ __align__(16) __half st[64 * 104];
    const float beta2 = 2.25f * bw[1];
    const float beta3 = (300.0f / 9.0f) * bw[2];

    #pragma unroll
    for (int it = 0; it < 8; ++it) {
        const int ci = it * 4 + cisub;
        float v = x[((size_t)(n * CI + ci) * HH + h) * WW + w0 + pix];
        float t = tanh_fast(v);
        float p2 = t * t - beta2;
        float p3 = t * p2 - beta3 * t;
        st[pix * 104 + ci]      = __float2half_rn(silu_fast(t));
        st[pix * 104 + 32 + ci] = __float2half_rn(silu_fast(p2));
        st[pix * 104 + 64 + ci] = __float2half_rn(silu_fast(p3));
    }
    __syncthreads();

    uint4* gout4 = reinterpret_cast<uint4*>(
        g_scratch + ((size_t)(n * HH + h) * WW + w0) * GC96);
    const uint4* st4 = reinterpret_cast<const uint4*>(st);
    #pragma unroll
    for (int it = 0; it < 3; ++it) {
        int f4 = it * 256 + tid;
        int p = f4 / 12, c4 = f4 - p * 12;
        gout4[f4] = st4[p * 13 + c4];
    }
}

// ---------------------------------------------------------------------------
// K3: conv, 16x32 tile, 4 rows/warp, kw-major A-reuse (R13 design).
// Buffer: g 34*18*48B = 29376B + w 9216B = 38592B; double-buffered.
// ---------------------------------------------------------------------------
#define BUFFB 38592
#define WOFFB 29376

__global__ __launch_bounds__(256, 2) void conv_kernel(float* __restrict__ out) {
    extern __shared__ char smc[];
    const int n = blockIdx.z;
    const int x0 = blockIdx.x * 16;
    const int y0 = blockIdx.y * 32;
    const int tid = threadIdx.x;
    const int lane = tid & 31;
    const int wid = tid >> 5;
    const int g = lane >> 2;
    const int t = lane & 3;

    uint32_t smbase;
    asm("{ .reg .u64 tt; cvta.to.shared.u64 tt, %1; cvt.u32.u64 %0, tt; }"
        : "=r"(smbase) : "l"(smc));
    const uint32_t alane = (uint32_t)(lane & 15) * 48u + (uint32_t)(lane >> 4) * 16u;

    float acc[4][4][4];
    #pragma unroll
    for (int b = 0; b < 4; ++b)
        #pragma unroll
        for (int c = 0; c < 4; ++c)
            #pragma unroll
            for (int d = 0; d < 4; ++d) acc[b][c][d] = 0.0f;

    // ---- prefetch: 34*18*2 = 1224 g-cp16 + 576 w-cp16
    auto prefetch = [&](int ch, int buf) {
        uint32_t base = smbase + (uint32_t)buf * BUFFB;
        for (int i = tid; i < 1224; i += 256) {
            int plane = i & 1;
            int pos = i >> 1;
            int r = pos / 18;
            int c = pos - r * 18;
            int gy = y0 - 1 + r, gx = x0 - 1 + c;
            int ok = ((unsigned)gy < 192u) & ((unsigned)gx < 192u);
            int cgy = ok ? gy : 0, cgx = ok ? gx : 0;
            const __half* src = g_scratch + (((size_t)n * HH + cgy) * WW + cgx) * GC96
                                + ch * 16 + plane * 8;
            uint32_t dst = base + (uint32_t)(r * 864 + c * 48 + plane * 16);
            cp16(dst, src, ok ? 16 : 0);
        }
        const __half* wsrc = w_prep + ch * 4608;
        uint32_t wdst = base + WOFFB;
        for (int i = tid; i < 576; i += 256)
            cp16(wdst + (uint32_t)i * 16u, wsrc + i * 8, 16);
    };

    prefetch(0, 0); CP_COMMIT();

    for (int ch = 0; ch < 6; ++ch) {
        if (ch < 5) {
            prefetch(ch + 1, (ch + 1) & 1);
            CP_COMMIT();
            CP_WAIT(1);
        } else {
            CP_WAIT(0);
        }
        __syncthreads();

        const int buf = ch & 1;
        const uint32_t abase = smbase + (uint32_t)buf * BUFFB + alane;
        const uint32_t wbase = smbase + (uint32_t)buf * BUFFB + WOFFB
                               + (uint32_t)lane * 16u;

        #pragma unroll
        for (int kw = 0; kw < 3; ++kw) {
            // 6 A fragments: tile rows 4wid..4wid+5, columns kw..kw+15
            unsigned A[6][4];
            #pragma unroll
            for (int j = 0; j < 6; ++j) {
                uint32_t addr = abase + (uint32_t)((4 * wid + j) * 864 + kw * 48);
                asm volatile("ldmatrix.sync.aligned.m8n8.x4.shared.b16 "
                             "{%0,%1,%2,%3}, [%4];"
                             : "=r"(A[j][0]), "=r"(A[j][1]),
                               "=r"(A[j][2]), "=r"(A[j][3])
                             : "r"(addr));
            }
            #pragma unroll
            for (int kh = 0; kh < 3; ++kh) {
                const int tap = kh * 3 + kw;
                unsigned b0[4], b1[4];
                #pragma unroll
                for (int p = 0; p < 2; ++p) {
                    uint32_t waddr = wbase + (uint32_t)(tap * 1024 + p * 512);
                    asm volatile("ldmatrix.sync.aligned.m8n8.x4.shared.b16 "
                                 "{%0,%1,%2,%3}, [%4];"
                                 : "=r"(b0[2 * p]), "=r"(b1[2 * p]),
                                   "=r"(b0[2 * p + 1]), "=r"(b1[2 * p + 1])
                                 : "r"(waddr));
                }
                #pragma unroll
                for (int mrow = 0; mrow < 4; ++mrow) {
                    const int j = mrow + kh;
                    #pragma unroll
                    for (int nc = 0; nc < 4; ++nc)
                        mma_f16(acc[mrow][nc], A[j][0], A[j][1], A[j][2], A[j][3],
                                b0[nc], b1[nc]);
                }
            }
        }
        __syncthreads();   // protect buf from next iteration's prefetch
    }

    // ---- epilogue: + basis0 bias, * gate scale
    const float s = s_scale_s[n];
    #pragma unroll
    for (int mrow = 0; mrow < 4; ++mrow) {
        const int y = y0 + 4 * wid + mrow;
        const int ry = (y == 0) ? 0 : ((y == HH - 1) ? 2 : 1);
        #pragma unroll
        for (int nc = 0; nc < 4; ++nc) {
            #pragma unroll
            for (int e = 0; e < 4; ++e) {
                const int px = g + ((e >= 2) ? 8 : 0);
                const int oc = 8 * nc + 2 * t + (e & 1);
                const int xx = x0 + px;
                const int cx = (xx == 0) ? 0 : ((xx == WW - 1) ? 2 : 1);
                out[((size_t)(n * CI + oc) * HH + y) * WW + xx] =
                    (acc[mrow][nc][e] + bias_g[(ry * 3 + cx) * CI + oc]) * s;
            }
        }
    }
}

// ---------------------------------------------------------------------------
extern "C" void kernel_launch(void* const* d_in, const int* in_sizes, int n_in,
                              void* d_out, int out_size) {
    const float* x  = (const float*)d_in[0];
    const float* wg = (const float*)d_in[1];
    const float* W  = (const float*)d_in[2];
    const float* bw = (const float*)d_in[3];
    float* out = (float*)d_out;
    const int loss_idx = out_size - 1;

    cudaFuncSetAttribute(conv_kernel, cudaFuncAttributeMaxDynamicSharedMemorySize,
                         BUFFB * 2);

    gate_mean_kernel<<<NB * CI, 256>>>(x);
    prep_kernel<<<110, 256>>>(W, wg, out, loss_idx);
    basis_kernel<<<dim3(3, 192, 16), 256>>>(x, bw);
    conv_kernel<<<dim3(12, 6, 16), 256, BUFFB * 2>>>(out);
}